// round 7
// baseline (speedup 1.0000x reference)
#include <cuda_runtime.h>
#include <cuda_bf16.h>
#include <stdint.h>

#define BB 2
#define EE 512
#define NN 4096
#define MM 4096

typedef unsigned long long u64;
typedef unsigned int u32;

// ---- scratch ---------------------------------------------------------------
__device__ __nv_bfloat16 g_Qhi[BB * NN * EE];
__device__ __nv_bfloat16 g_Qlo[BB * NN * EE];
__device__ __nv_bfloat16 g_Khi[BB * MM * EE];
__device__ __nv_bfloat16 g_Klo[BB * MM * EE];
__device__ float g_kk[BB * MM];
__device__ float g_pm[4 * BB * NN], g_pl[4 * BB * NN], g_po[4 * BB * NN * 3];

// ---- f32x2 helpers ---------------------------------------------------------
__device__ __forceinline__ u64 pack2(float x) {
    u64 r; asm("mov.b64 %0, {%1, %1};" : "=l"(r) : "f"(x)); return r;
}
__device__ __forceinline__ void fma2(u64& d, u64 a, u64 b) {
    asm("fma.rn.f32x2 %0, %1, %2, %3;" : "=l"(d) : "l"(a), "l"(b), "l"(d));
}
__device__ __forceinline__ float2 unpack2(u64 v) {
    float2 f; asm("mov.b64 {%0, %1}, %2;" : "=f"(f.x), "=f"(f.y) : "l"(v)); return f;
}

// ---- PTX helpers (portable, no 'a'-features) -------------------------------
__device__ __forceinline__ u32 smem_u32(const void* p) {
    u32 a;
    asm("{ .reg .u64 t; cvta.to.shared.u64 t, %1; cvt.u32.u64 %0, t; }" : "=r"(a) : "l"(p));
    return a;
}
__device__ __forceinline__ void cp16(u32 dst, const void* src) {
    asm volatile("cp.async.cg.shared.global [%0], [%1], 16;" :: "r"(dst), "l"(src) : "memory");
}
#define CP_COMMIT() asm volatile("cp.async.commit_group;" ::: "memory")
#define CP_WAIT(n)  asm volatile("cp.async.wait_group %0;" :: "n"(n) : "memory")

__device__ __forceinline__ void ldsm4(u32* r, u32 a) {
    asm volatile("ldmatrix.sync.aligned.m8n8.x4.shared.b16 {%0,%1,%2,%3}, [%4];"
                 : "=r"(r[0]), "=r"(r[1]), "=r"(r[2]), "=r"(r[3]) : "r"(a));
}
__device__ __forceinline__ void mma16816(float* c, const u32* a, const u32* b) {
    asm volatile(
        "mma.sync.aligned.m16n8k16.row.col.f32.bf16.bf16.f32 "
        "{%0,%1,%2,%3}, {%4,%5,%6,%7}, {%8,%9}, {%0,%1,%2,%3};"
        : "+f"(c[0]), "+f"(c[1]), "+f"(c[2]), "+f"(c[3])
        : "r"(a[0]), "r"(a[1]), "r"(a[2]), "r"(a[3]), "r"(b[0]), "r"(b[1]));
}
__device__ __forceinline__ u32 bf2_u32(float a, float b) {
    __nv_bfloat162 t = __floats2bfloat162_rn(a, b);
    return *reinterpret_cast<u32*>(&t);
}

// ---------------------------------------------------------------------------
// Projection -> bf16 hi/lo [b][n][e]
// ---------------------------------------------------------------------------
__global__ __launch_bounds__(256) void proj_kernel(
    const float* __restrict__ X, const float* __restrict__ W,
    const float* __restrict__ bias, int which)
{
    __nv_bfloat16* __restrict__ Yh = which ? g_Khi : g_Qhi;
    __nv_bfloat16* __restrict__ Yl = which ? g_Klo : g_Qlo;
    __shared__ float Xs[32][64];
    __shared__ float Ws[32][128];

    const int tid = threadIdx.x;
    const int tx = tid & 15, ty = tid >> 4;
    const int n0 = blockIdx.x * 64, f0 = blockIdx.y * 128, b = blockIdx.z;

    u64 acc[4][4];
#pragma unroll
    for (int i = 0; i < 4; ++i)
#pragma unroll
        for (int j = 0; j < 4; ++j) acc[i][j] = 0ull;

    const float* Xb = X + (size_t)b * EE * NN;
    for (int e0 = 0; e0 < EE; e0 += 32) {
        {
            const int r = tid >> 3, c = (tid & 7) * 8;
            const float4* s4 = (const float4*)(Xb + (size_t)(e0 + r) * NN + n0 + c);
            float4 v0 = s4[0], v1 = s4[1];
            *(float4*)&Xs[r][c] = v0; *(float4*)&Xs[r][c + 4] = v1;
        }
        {
            const int f = tid >> 1, eo = (tid & 1) * 16;
            const float4* w4 = (const float4*)(W + (size_t)(f0 + f) * EE + e0 + eo);
#pragma unroll
            for (int k = 0; k < 4; ++k) {
                float4 v = w4[k];
                Ws[eo + 4*k + 0][f] = v.x; Ws[eo + 4*k + 1][f] = v.y;
                Ws[eo + 4*k + 2][f] = v.z; Ws[eo + 4*k + 3][f] = v.w;
            }
        }
        __syncthreads();
#pragma unroll 8
        for (int e = 0; e < 32; ++e) {
            float4 a = *(const float4*)&Xs[e][ty * 4];
            ulonglong2 b0 = *(const ulonglong2*)&Ws[e][tx * 4];
            ulonglong2 b1 = *(const ulonglong2*)&Ws[e][64 + tx * 4];
            u64 ap;
            ap = pack2(a.x);
            fma2(acc[0][0], ap, b0.x); fma2(acc[0][1], ap, b0.y);
            fma2(acc[0][2], ap, b1.x); fma2(acc[0][3], ap, b1.y);
            ap = pack2(a.y);
            fma2(acc[1][0], ap, b0.x); fma2(acc[1][1], ap, b0.y);
            fma2(acc[1][2], ap, b1.x); fma2(acc[1][3], ap, b1.y);
            ap = pack2(a.z);
            fma2(acc[2][0], ap, b0.x); fma2(acc[2][1], ap, b0.y);
            fma2(acc[2][2], ap, b1.x); fma2(acc[2][3], ap, b1.y);
            ap = pack2(a.w);
            fma2(acc[3][0], ap, b0.x); fma2(acc[3][1], ap, b0.y);
            fma2(acc[3][2], ap, b1.x); fma2(acc[3][3], ap, b1.y);
        }
        __syncthreads();
    }

    float4 bs0 = *(const float4*)(bias + f0 + tx * 4);
    float4 bs1 = *(const float4*)(bias + f0 + 64 + tx * 4);
    float bv[8] = {bs0.x, bs0.y, bs0.z, bs0.w, bs1.x, bs1.y, bs1.z, bs1.w};
#pragma unroll
    for (int i = 0; i < 4; ++i) {
        float y[8]; float2 p;
        p = unpack2(acc[i][0]); y[0] = p.x + bv[0]; y[1] = p.y + bv[1];
        p = unpack2(acc[i][1]); y[2] = p.x + bv[2]; y[3] = p.y + bv[3];
        p = unpack2(acc[i][2]); y[4] = p.x + bv[4]; y[5] = p.y + bv[5];
        p = unpack2(acc[i][3]); y[6] = p.x + bv[6]; y[7] = p.y + bv[7];
        float hf[8], lf[8];
#pragma unroll
        for (int j = 0; j < 8; ++j) {
            __nv_bfloat16 h = __float2bfloat16_rn(y[j]);
            hf[j] = __bfloat162float(h);
            lf[j] = y[j] - hf[j];
        }
        const size_t rowo = ((size_t)b * NN + n0 + ty * 4 + i) * EE;
#pragma unroll
        for (int g = 0; g < 2; ++g) {
            uint2 ph, pl;
            ph.x = bf2_u32(hf[g*4+0], hf[g*4+1]); ph.y = bf2_u32(hf[g*4+2], hf[g*4+3]);
            pl.x = bf2_u32(lf[g*4+0], lf[g*4+1]); pl.y = bf2_u32(lf[g*4+2], lf[g*4+3]);
            const size_t off = rowo + f0 + g * 64 + tx * 4;
            *(uint2*)(Yh + off) = ph;
            *(uint2*)(Yl + off) = pl;
        }
    }
}

// ---------------------------------------------------------------------------
__global__ __launch_bounds__(256) void kk_kernel()
{
    const int row = blockIdx.x * 8 + (threadIdx.x >> 5);
    const int lane = threadIdx.x & 31;
    const uint4* h4 = (const uint4*)(g_Khi + (size_t)row * EE);
    const uint4* l4 = (const uint4*)(g_Klo + (size_t)row * EE);
    float s = 0.f;
#pragma unroll
    for (int it = 0; it < 2; ++it) {
        uint4 h = h4[lane + it * 32], l = l4[lane + it * 32];
        const __nv_bfloat162* hp = (const __nv_bfloat162*)&h;
        const __nv_bfloat162* lp = (const __nv_bfloat162*)&l;
#pragma unroll
        for (int k = 0; k < 4; ++k) {
            float2 fh = __bfloat1622float2(hp[k]);
            float2 fl = __bfloat1622float2(lp[k]);
            float x = fh.x + fl.x, y = fh.y + fl.y;
            s = fmaf(x, x, fmaf(y, y, s));
        }
    }
#pragma unroll
    for (int off = 16; off; off >>= 1) s += __shfl_xor_sync(0xffffffffu, s, off);
    if (lane == 0) g_kk[row] = s;
}

// ---------------------------------------------------------------------------
// mma.sync attention, 2 CTAs/SM. grid 256: b = bx>>7, q-tile = bx&127 (32 rows).
// CTA 32q x 128k tiles; 8 warps = 2(q) x 4(k); warp tile 16x32; 3-term split.
// ---------------------------------------------------------------------------
#define QPITCH 1040
#define SM_QH 0
#define SM_QL 33280
#define SM_K  66560          /* [2 buf][hi/lo][128 keys][KPITCH] */
#define KPITCH 80
#define KLO_OFF 10240
#define KBUF 20480
#define SM_KKS 107520
#define SM_TGS 108032
#define SMEM_TOTAL 109568

__global__ __launch_bounds__(256, 2) void attn_kernel(const float* __restrict__ tgt)
{
    extern __shared__ char smraw[];
    const u32 S = smem_u32(smraw);
    const int tid = threadIdx.x, wid = tid >> 5, lane = tid & 31;
    const int qg = wid >> 2, kg = wid & 3;
    const int b = blockIdx.x >> 7, n0 = (blockIdx.x & 127) * 32;

    // ---- Q tile fill (once): 32 rows x 512 e, hi+lo ----
    {
        const char* qh = (const char*)(g_Qhi + (size_t)(b * NN + n0) * EE);
        const char* ql = (const char*)(g_Qlo + (size_t)(b * NN + n0) * EE);
        for (int i = tid; i < 2048; i += 256) {
            const int row = i >> 6, g = (i & 63) * 16;
            cp16(S + SM_QH + row * QPITCH + g, qh + row * 1024 + g);
            cp16(S + SM_QL + row * QPITCH + g, ql + row * 1024 + g);
        }
        CP_COMMIT(); CP_WAIT(0);
        __syncthreads();
    }

    // lane-constant ldmatrix offsets
    const int laneQrow = (lane & 7) + ((lane >> 3) & 1) * 8;
    const int laneQcolB = (lane >> 4) * 16;
    const int laneKn = (lane & 7) + ((lane >> 4) & 1) * 8;
    const int laneKeB = ((lane >> 3) & 1) * 16;
    const u32 qoff = (u32)((qg * 16 + laneQrow) * QPITCH + laneQcolB);
    u32 koff[2];
#pragma unroll
    for (int np = 0; np < 2; ++np)
        koff[np] = (u32)((kg * 32 + np * 16 + laneKn) * KPITCH + laneKeB);

    float* kks = (float*)(smraw + SM_KKS);
    float* tgs = (float*)(smraw + SM_TGS);
    const float* kkb = g_kk + b * MM;
    const float* tgtb = tgt + (size_t)b * 3 * MM;

    float stm[2], stl[2], so[2][3];
#pragma unroll
    for (int r = 0; r < 2; ++r) {
        stm[r] = -1e30f; stl[r] = 0.f;
        so[r][0] = so[r][1] = so[r][2] = 0.f;
    }

    for (int t = 0; t < 32; ++t) {
        const int m0 = t * 128;
        const char* khg = (const char*)(g_Khi + (size_t)(b * MM + m0) * EE);
        const char* klg = (const char*)(g_Klo + (size_t)(b * MM + m0) * EE);
        __syncthreads();                        // prior epilogue done with kks/tgs
        if (tid < 128) kks[tid] = kkb[m0 + tid];
        for (int i = tid; i < 384; i += 256)
            tgs[i] = tgtb[(i >> 7) * MM + m0 + (i & 127)];

        float acc[4][4];
#pragma unroll
        for (int nt = 0; nt < 4; ++nt)
#pragma unroll
            for (int j = 0; j < 4; ++j) acc[nt][j] = 0.f;

        // fill chunk 0 -> buf 0  (128 keys x 64 bytes = 512 granules)
        for (int i = tid; i < 512; i += 256) {
            const int key = i >> 2, g = (i & 3) * 16;
            cp16(S + SM_K + key * KPITCH + g, khg + key * 1024 + g);
            cp16(S + SM_K + KLO_OFF + key * KPITCH + g, klg + key * 1024 + g);
        }
        CP_COMMIT();

        for (int c = 0; c < 16; ++c) {
            if (c < 15) {
                const u32 dst = S + SM_K + ((c + 1) & 1) * KBUF;
                const int go = (c + 1) * 64;
                for (int i = tid; i < 512; i += 256) {
                    const int key = i >> 2, g = (i & 3) * 16;
                    cp16(dst + key * KPITCH + g, khg + key * 1024 + go + g);
                    cp16(dst + KLO_OFF + key * KPITCH + g, klg + key * 1024 + go + g);
                }
                CP_COMMIT(); CP_WAIT(1);
            } else {
                CP_WAIT(0);
            }
            __syncthreads();
            const u32 KB = S + SM_K + (c & 1) * KBUF;
#pragma unroll
            for (int s = 0; s < 2; ++s) {
                const u32 qeB = (u32)(c * 64 + s * 32);
                const u32 keB = (u32)(s * 32);
                u32 ah[4], al[4], bh[2][4], bl[2][4];
                ldsm4(ah, S + SM_QH + qoff + qeB);
                ldsm4(al, S + SM_QL + qoff + qeB);
#pragma unroll
                for (int np = 0; np < 2; ++np) {
                    ldsm4(bh[np], KB + koff[np] + keB);
                    ldsm4(bl[np], KB + KLO_OFF + koff[np] + keB);
                }
#pragma unroll
                for (int np = 0; np < 2; ++np) {
                    mma16816(acc[np*2+0], ah, &bh[np][0]);
                    mma16816(acc[np*2+0], ah, &bl[np][0]);
                    mma16816(acc[np*2+0], al, &bh[np][0]);
                    mma16816(acc[np*2+1], ah, &bh[np][2]);
                    mma16816(acc[np*2+1], ah, &bl[np][2]);
                    mma16816(acc[np*2+1], al, &bh[np][2]);
                }
            }
            __syncthreads();
        }

        // ---- epilogue: online softmax, per-thread 2 rows x 8 cols ----
#pragma unroll
        for (int h = 0; h < 2; ++h) {
            float lg[8], vmax = -1e30f;
#pragma unroll
            for (int nt = 0; nt < 4; ++nt) {
                const int cb = kg * 32 + nt * 8 + (lane & 3) * 2;
                lg[2*nt]   = fmaf(2.f, acc[nt][h*2+0], -kks[cb]);
                lg[2*nt+1] = fmaf(2.f, acc[nt][h*2+1], -kks[cb+1]);
                vmax = fmaxf(vmax, fmaxf(lg[2*nt], lg[2*nt+1]));
            }
            if (vmax >= stm[h] - 30.f) {        // skip: adds < 3e-9 rel error
                const float nm = fmaxf(stm[h], vmax);
                const float sc = __expf(stm[h] - nm);
                stl[h] *= sc; so[h][0] *= sc; so[h][1] *= sc; so[h][2] *= sc;
#pragma unroll
                for (int j = 0; j < 8; ++j) {
                    const int cb = kg * 32 + (j >> 1) * 8 + (lane & 3) * 2 + (j & 1);
                    const float p = __expf(lg[j] - nm);
                    stl[h] += p;
                    so[h][0] = fmaf(p, tgs[cb], so[h][0]);
                    so[h][1] = fmaf(p, tgs[128 + cb], so[h][1]);
                    so[h][2] = fmaf(p, tgs[256 + cb], so[h][2]);
                }
                stm[h] = nm;
            }
        }
    }

    // ---- merge across the 4 lanes sharing each row, write partials ----
#pragma unroll
    for (int h = 0; h < 2; ++h) {
        float m = stm[h], l = stl[h];
        float o0 = so[h][0], o1 = so[h][1], o2 = so[h][2];
#pragma unroll
        for (int off = 1; off < 4; off <<= 1) {
            float om = __shfl_xor_sync(0xffffffffu, m,  off, 4);
            float ol = __shfl_xor_sync(0xffffffffu, l,  off, 4);
            float p0 = __shfl_xor_sync(0xffffffffu, o0, off, 4);
            float p1 = __shfl_xor_sync(0xffffffffu, o1, off, 4);
            float p2 = __shfl_xor_sync(0xffffffffu, o2, off, 4);
            const float nm = fmaxf(m, om);
            const float sa = __expf(m - nm), sb = __expf(om - nm);
            l = l * sa + ol * sb;
            o0 = o0 * sa + p0 * sb; o1 = o1 * sa + p1 * sb; o2 = o2 * sa + p2 * sb;
            m = nm;
        }
        if ((lane & 3) == 0) {
            const int n = n0 + qg * 16 + h * 8 + (lane >> 2);
            const size_t pidx = (size_t)kg * (BB * NN) + (size_t)b * NN + n;
            g_pm[pidx] = m; g_pl[pidx] = l;
            g_po[3 * pidx + 0] = o0; g_po[3 * pidx + 1] = o1; g_po[3 * pidx + 2] = o2;
        }
    }
}

// ---------------------------------------------------------------------------
__global__ void merge_kernel(float* __restrict__ out_corr)
{
    const int idx = blockIdx.x * 256 + threadIdx.x;
    if (idx >= BB * NN) return;
    const int b = idx >> 12, n = idx & (NN - 1);
    float m = -1e30f;
#pragma unroll
    for (int s = 0; s < 4; ++s) m = fmaxf(m, g_pm[s * BB * NN + idx]);
    float l = 0.f, o0 = 0.f, o1 = 0.f, o2 = 0.f;
#pragma unroll
    for (int s = 0; s < 4; ++s) {
        const size_t p = (size_t)s * BB * NN + idx;
        const float w = __expf(g_pm[p] - m);
        l += g_pl[p] * w;
        o0 += g_po[3 * p + 0] * w; o1 += g_po[3 * p + 1] * w; o2 += g_po[3 * p + 2] * w;
    }
    const float inv = 1.f / l;
    out_corr[((size_t)b * 3 + 0) * NN + n] = o0 * inv;
    out_corr[((size_t)b * 3 + 1) * NN + n] = o1 * inv;
    out_corr[((size_t)b * 3 + 2) * NN + n] = o2 * inv;
}

__global__ void copy_src_kernel(const float* __restrict__ src, float* __restrict__ out)
{
    const int i = blockIdx.x * 256 + threadIdx.x;
    if (i < BB * 3 * NN) out[i] = src[i];
}

// ---------------------------------------------------------------------------
extern "C" void kernel_launch(void* const* d_in, const int* in_sizes, int n_in,
                              void* d_out, int out_size)
{
    const float* src_emb = (const float*)d_in[0];
    const float* tgt_emb = (const float*)d_in[1];
    const float* src     = (const float*)d_in[2];
    const float* tgt     = (const float*)d_in[3];
    const float* Wq      = (const float*)d_in[4];
    const float* bq      = (const float*)d_in[5];
    const float* Wk      = (const float*)d_in[6];
    const float* bk      = (const float*)d_in[7];
    float* out = (float*)d_out;

    const int corr_elems = BB * 3 * NN;
    const bool tuple_out = (out_size >= 2 * corr_elems);
    float* corr_out = tuple_out ? (out + corr_elems) : out;

    dim3 pg(NN / 64, EE / 128, BB);
    proj_kernel<<<pg, 256>>>(src_emb, Wq, bq, 0);
    proj_kernel<<<pg, 256>>>(tgt_emb, Wk, bk, 1);
    kk_kernel<<<BB * MM / 8, 256>>>();

    cudaFuncSetAttribute(attn_kernel, cudaFuncAttributeMaxDynamicSharedMemorySize,
                         SMEM_TOTAL);
    attn_kernel<<<256, 256, SMEM_TOTAL>>>(tgt);

    merge_kernel<<<(BB * NN + 255) / 256, 256>>>(corr_out);
    if (tuple_out)
        copy_src_kernel<<<(corr_elems + 255) / 256, 256>>>(src, out);
}

// round 8
// speedup vs baseline: 1.1377x; 1.1377x over previous
#include <cuda_runtime.h>
#include <cuda_bf16.h>
#include <stdint.h>

#define BB 2
#define EE 512
#define NN 4096
#define MM 4096

typedef unsigned long long u64;
typedef unsigned int u32;

// ---- scratch ---------------------------------------------------------------
__device__ __nv_bfloat16 g_Qhi[BB * NN * EE];
__device__ __nv_bfloat16 g_Qlo[BB * NN * EE];
__device__ __nv_bfloat16 g_Khi[BB * MM * EE];
__device__ __nv_bfloat16 g_Klo[BB * MM * EE];
__device__ float g_kk[BB * MM];
__device__ float g_pm[16 * BB * NN], g_pl[16 * BB * NN], g_po[16 * BB * NN * 3];

// ---- f32x2 helpers ---------------------------------------------------------
__device__ __forceinline__ u64 pack2(float x) {
    u64 r; asm("mov.b64 %0, {%1, %1};" : "=l"(r) : "f"(x)); return r;
}
__device__ __forceinline__ void fma2(u64& d, u64 a, u64 b) {
    asm("fma.rn.f32x2 %0, %1, %2, %3;" : "=l"(d) : "l"(a), "l"(b), "l"(d));
}
__device__ __forceinline__ float2 unpack2(u64 v) {
    float2 f; asm("mov.b64 {%0, %1}, %2;" : "=f"(f.x), "=f"(f.y) : "l"(v)); return f;
}

// ---- PTX helpers (portable, no 'a'-features) -------------------------------
__device__ __forceinline__ u32 smem_u32(const void* p) {
    u32 a;
    asm("{ .reg .u64 t; cvta.to.shared.u64 t, %1; cvt.u32.u64 %0, t; }" : "=r"(a) : "l"(p));
    return a;
}
__device__ __forceinline__ void cp16(u32 dst, const void* src) {
    asm volatile("cp.async.cg.shared.global [%0], [%1], 16;" :: "r"(dst), "l"(src) : "memory");
}
#define CP_COMMIT() asm volatile("cp.async.commit_group;" ::: "memory")
#define CP_WAIT0()  asm volatile("cp.async.wait_group 0;" ::: "memory")

__device__ __forceinline__ void ldsm4(u32* r, u32 a) {
    asm volatile("ldmatrix.sync.aligned.m8n8.x4.shared.b16 {%0,%1,%2,%3}, [%4];"
                 : "=r"(r[0]), "=r"(r[1]), "=r"(r[2]), "=r"(r[3]) : "r"(a));
}
__device__ __forceinline__ void mma16816(float* c, const u32* a, const u32* b) {
    asm volatile(
        "mma.sync.aligned.m16n8k16.row.col.f32.bf16.bf16.f32 "
        "{%0,%1,%2,%3}, {%4,%5,%6,%7}, {%8,%9}, {%0,%1,%2,%3};"
        : "+f"(c[0]), "+f"(c[1]), "+f"(c[2]), "+f"(c[3])
        : "r"(a[0]), "r"(a[1]), "r"(a[2]), "r"(a[3]), "r"(b[0]), "r"(b[1]));
}
__device__ __forceinline__ u32 bf2_u32(float a, float b) {
    __nv_bfloat162 t = __floats2bfloat162_rn(a, b);
    return *reinterpret_cast<u32*>(&t);
}

// ---------------------------------------------------------------------------
// Projection -> bf16 hi/lo [b][n][e]
// ---------------------------------------------------------------------------
__global__ __launch_bounds__(256) void proj_kernel(
    const float* __restrict__ X, const float* __restrict__ W,
    const float* __restrict__ bias, int which)
{
    __nv_bfloat16* __restrict__ Yh = which ? g_Khi : g_Qhi;
    __nv_bfloat16* __restrict__ Yl = which ? g_Klo : g_Qlo;
    __shared__ float Xs[32][64];
    __shared__ float Ws[32][128];

    const int tid = threadIdx.x;
    const int tx = tid & 15, ty = tid >> 4;
    const int n0 = blockIdx.x * 64, f0 = blockIdx.y * 128, b = blockIdx.z;

    u64 acc[4][4];
#pragma unroll
    for (int i = 0; i < 4; ++i)
#pragma unroll
        for (int j = 0; j < 4; ++j) acc[i][j] = 0ull;

    const float* Xb = X + (size_t)b * EE * NN;
    for (int e0 = 0; e0 < EE; e0 += 32) {
        {
            const int r = tid >> 3, c = (tid & 7) * 8;
            const float4* s4 = (const float4*)(Xb + (size_t)(e0 + r) * NN + n0 + c);
            float4 v0 = s4[0], v1 = s4[1];
            *(float4*)&Xs[r][c] = v0; *(float4*)&Xs[r][c + 4] = v1;
        }
        {
            const int f = tid >> 1, eo = (tid & 1) * 16;
            const float4* w4 = (const float4*)(W + (size_t)(f0 + f) * EE + e0 + eo);
#pragma unroll
            for (int k = 0; k < 4; ++k) {
                float4 v = w4[k];
                Ws[eo + 4*k + 0][f] = v.x; Ws[eo + 4*k + 1][f] = v.y;
                Ws[eo + 4*k + 2][f] = v.z; Ws[eo + 4*k + 3][f] = v.w;
            }
        }
        __syncthreads();
#pragma unroll 8
        for (int e = 0; e < 32; ++e) {
            float4 a = *(const float4*)&Xs[e][ty * 4];
            ulonglong2 b0 = *(const ulonglong2*)&Ws[e][tx * 4];
            ulonglong2 b1 = *(const ulonglong2*)&Ws[e][64 + tx * 4];
            u64 ap;
            ap = pack2(a.x);
            fma2(acc[0][0], ap, b0.x); fma2(acc[0][1], ap, b0.y);
            fma2(acc[0][2], ap, b1.x); fma2(acc[0][3], ap, b1.y);
            ap = pack2(a.y);
            fma2(acc[1][0], ap, b0.x); fma2(acc[1][1], ap, b0.y);
            fma2(acc[1][2], ap, b1.x); fma2(acc[1][3], ap, b1.y);
            ap = pack2(a.z);
            fma2(acc[2][0], ap, b0.x); fma2(acc[2][1], ap, b0.y);
            fma2(acc[2][2], ap, b1.x); fma2(acc[2][3], ap, b1.y);
            ap = pack2(a.w);
            fma2(acc[3][0], ap, b0.x); fma2(acc[3][1], ap, b0.y);
            fma2(acc[3][2], ap, b1.x); fma2(acc[3][3], ap, b1.y);
        }
        __syncthreads();
    }

    float4 bs0 = *(const float4*)(bias + f0 + tx * 4);
    float4 bs1 = *(const float4*)(bias + f0 + 64 + tx * 4);
    float bv[8] = {bs0.x, bs0.y, bs0.z, bs0.w, bs1.x, bs1.y, bs1.z, bs1.w};
#pragma unroll
    for (int i = 0; i < 4; ++i) {
        float y[8]; float2 p;
        p = unpack2(acc[i][0]); y[0] = p.x + bv[0]; y[1] = p.y + bv[1];
        p = unpack2(acc[i][1]); y[2] = p.x + bv[2]; y[3] = p.y + bv[3];
        p = unpack2(acc[i][2]); y[4] = p.x + bv[4]; y[5] = p.y + bv[5];
        p = unpack2(acc[i][3]); y[6] = p.x + bv[6]; y[7] = p.y + bv[7];
        float hf[8], lf[8];
#pragma unroll
        for (int j = 0; j < 8; ++j) {
            __nv_bfloat16 h = __float2bfloat16_rn(y[j]);
            hf[j] = __bfloat162float(h);
            lf[j] = y[j] - hf[j];
        }
        const size_t rowo = ((size_t)b * NN + n0 + ty * 4 + i) * EE;
#pragma unroll
        for (int g = 0; g < 2; ++g) {
            uint2 ph, pl;
            ph.x = bf2_u32(hf[g*4+0], hf[g*4+1]); ph.y = bf2_u32(hf[g*4+2], hf[g*4+3]);
            pl.x = bf2_u32(lf[g*4+0], lf[g*4+1]); pl.y = bf2_u32(lf[g*4+2], lf[g*4+3]);
            const size_t off = rowo + f0 + g * 64 + tx * 4;
            *(uint2*)(Yh + off) = ph;
            *(uint2*)(Yl + off) = pl;
        }
    }
}

// ---------------------------------------------------------------------------
__global__ __launch_bounds__(256) void kk_kernel()
{
    const int row = blockIdx.x * 8 + (threadIdx.x >> 5);
    const int lane = threadIdx.x & 31;
    const uint4* h4 = (const uint4*)(g_Khi + (size_t)row * EE);
    const uint4* l4 = (const uint4*)(g_Klo + (size_t)row * EE);
    float s = 0.f;
#pragma unroll
    for (int it = 0; it < 2; ++it) {
        uint4 h = h4[lane + it * 32], l = l4[lane + it * 32];
        const __nv_bfloat162* hp = (const __nv_bfloat162*)&h;
        const __nv_bfloat162* lp = (const __nv_bfloat162*)&l;
#pragma unroll
        for (int k = 0; k < 4; ++k) {
            float2 fh = __bfloat1622float2(hp[k]);
            float2 fl = __bfloat1622float2(lp[k]);
            float x = fh.x + fl.x, y = fh.y + fl.y;
            s = fmaf(x, x, fmaf(y, y, s));
        }
    }
#pragma unroll
    for (int off = 16; off; off >>= 1) s += __shfl_xor_sync(0xffffffffu, s, off);
    if (lane == 0) g_kk[row] = s;
}

// ---------------------------------------------------------------------------
// mma.sync attention, 2 CTAs/SM, multistage 1-sync pipeline, m-split 4.
// grid (256, 4): b = bx>>7, q-tile = bx&127 (32 rows), split = by (1024 keys).
// ---------------------------------------------------------------------------
#define QPITCH 1040
#define SM_QH 0
#define SM_QL 33280
#define SM_K  66560          /* [2 buf][hi/lo][128 keys][KPITCH] */
#define KPITCH 80
#define KLO_OFF 10240
#define KBUF 20480
#define SM_KKS 107520
#define SM_TGS 108032
#define SMEM_TOTAL 109568

__global__ __launch_bounds__(256, 2) void attn_kernel(const float* __restrict__ tgt)
{
    extern __shared__ char smraw[];
    const u32 S = smem_u32(smraw);
    const int tid = threadIdx.x, wid = tid >> 5, lane = tid & 31;
    const int qg = wid >> 2, kg = wid & 3;
    const int b = blockIdx.x >> 7, n0 = (blockIdx.x & 127) * 32;
    const int split = blockIdx.y;
    const int mbase = split * 1024;

    // ---- Q tile fill (once): 32 rows x 512 e, hi+lo ----
    {
        const char* qh = (const char*)(g_Qhi + (size_t)(b * NN + n0) * EE);
        const char* ql = (const char*)(g_Qlo + (size_t)(b * NN + n0) * EE);
#pragma unroll
        for (int it = 0; it < 8; ++it) {
            const int i = tid + it * 256;
            const int row = i >> 6, g = (i & 63) * 16;
            cp16(S + SM_QH + row * QPITCH + g, qh + row * 1024 + g);
            cp16(S + SM_QL + row * QPITCH + g, ql + row * 1024 + g);
        }
        CP_COMMIT();
    }

    // lane-constant ldmatrix offsets
    const int laneQrow = (lane & 7) + ((lane >> 3) & 1) * 8;
    const int laneQcolB = (lane >> 4) * 16;
    const int laneKn = (lane & 7) + ((lane >> 4) & 1) * 8;
    const int laneKeB = ((lane >> 3) & 1) * 16;
    const u32 qoff = (u32)((qg * 16 + laneQrow) * QPITCH + laneQcolB);
    u32 koff[2];
#pragma unroll
    for (int np = 0; np < 2; ++np)
        koff[np] = (u32)((kg * 32 + np * 16 + laneKn) * KPITCH + laneKeB);

    // per-thread fill constants: 512 granules / 256 threads = 2 each (hi & lo)
    const u32 fk1 = (u32)((tid >> 2) * KPITCH + (tid & 3) * 16);
    const u32 fk2 = fk1 + 64 * KPITCH;
    const u32 fg1 = (u32)((tid >> 2) * 1024 + (tid & 3) * 16);
    const u32 fg2 = fg1 + 64 * 1024;

    float* kks = (float*)(smraw + SM_KKS);
    float* tgs = (float*)(smraw + SM_TGS);
    const float* kkb = g_kk + b * MM;
    const float* tgtb = tgt + (size_t)b * 3 * MM;

    float stm[2], stl[2], so[2][3];
#pragma unroll
    for (int r = 0; r < 2; ++r) {
        stm[r] = -1e30f; stl[r] = 0.f;
        so[r][0] = so[r][1] = so[r][2] = 0.f;
    }

    for (int t = 0; t < 8; ++t) {
        const int m0 = mbase + t * 128;
        const char* khg = (const char*)(g_Khi + (size_t)(b * MM + m0) * EE);
        const char* klg = (const char*)(g_Klo + (size_t)(b * MM + m0) * EE);
        __syncthreads();                        // prior epilogue done with kks/tgs

        // kks/tgs via cp.async (tid 0..127), grouped with chunk-0 fill
        if (tid < 32) cp16(S + SM_KKS + tid * 16, kkb + m0 + tid * 4);
        else if (tid < 128) {
            const int idx = tid - 32;           // 0..95: 3 rows x 32 granules
            const int row = idx >> 5, c16 = idx & 31;
            cp16(S + SM_TGS + row * 512 + c16 * 16, tgtb + row * MM + m0 + c16 * 4);
        }
        // fill chunk 0 -> buf 0
        cp16(S + SM_K + fk1, khg + fg1);
        cp16(S + SM_K + fk2, khg + fg2);
        cp16(S + SM_K + KLO_OFF + fk1, klg + fg1);
        cp16(S + SM_K + KLO_OFF + fk2, klg + fg2);
        CP_COMMIT();

        float acc[4][4];
#pragma unroll
        for (int nt = 0; nt < 4; ++nt)
#pragma unroll
            for (int j = 0; j < 4; ++j) acc[nt][j] = 0.f;

        for (int c = 0; c < 16; ++c) {
            CP_WAIT0();                         // chunk c arrived (this thread)
            __syncthreads();                    // visible to all; buf[(c+1)&1] free
            if (c < 15) {                       // overlap fill(c+1) with compute(c)
                const u32 dst = S + SM_K + ((c + 1) & 1) * KBUF;
                const u32 go = (u32)((c + 1) * 64);
                cp16(dst + fk1, khg + fg1 + go);
                cp16(dst + fk2, khg + fg2 + go);
                cp16(dst + KLO_OFF + fk1, klg + fg1 + go);
                cp16(dst + KLO_OFF + fk2, klg + fg2 + go);
                CP_COMMIT();
            }
            const u32 KB = S + SM_K + (c & 1) * KBUF;
#pragma unroll
            for (int s = 0; s < 2; ++s) {
                const u32 qeB = (u32)(c * 64 + s * 32);
                const u32 keB = (u32)(s * 32);
                u32 ah[4], al[4], bh[2][4], bl[2][4];
                ldsm4(ah, S + SM_QH + qoff + qeB);
                ldsm4(al, S + SM_QL + qoff + qeB);
#pragma unroll
                for (int np = 0; np < 2; ++np) {
                    ldsm4(bh[np], KB + koff[np] + keB);
                    ldsm4(bl[np], KB + KLO_OFF + koff[np] + keB);
                }
#pragma unroll
                for (int np = 0; np < 2; ++np) {
                    mma16816(acc[np*2+0], ah, &bh[np][0]);
                    mma16816(acc[np*2+0], ah, &bl[np][0]);
                    mma16816(acc[np*2+0], al, &bh[np][0]);
                    mma16816(acc[np*2+1], ah, &bh[np][2]);
                    mma16816(acc[np*2+1], ah, &bl[np][2]);
                    mma16816(acc[np*2+1], al, &bh[np][2]);
                }
            }
        }

        // ---- epilogue: online softmax, per-thread 2 rows x 8 cols ----
#pragma unroll
        for (int h = 0; h < 2; ++h) {
            float lg[8], vmax = -1e30f;
#pragma unroll
            for (int nt = 0; nt < 4; ++nt) {
                const int cb = kg * 32 + nt * 8 + (lane & 3) * 2;
                lg[2*nt]   = fmaf(2.f, acc[nt][h*2+0], -kks[cb]);
                lg[2*nt+1] = fmaf(2.f, acc[nt][h*2+1], -kks[cb+1]);
                vmax = fmaxf(vmax, fmaxf(lg[2*nt], lg[2*nt+1]));
            }
            if (vmax >= stm[h] - 30.f) {        // skip: adds < 3e-9 rel error
                const float nm = fmaxf(stm[h], vmax);
                const float sc = __expf(stm[h] - nm);
                stl[h] *= sc; so[h][0] *= sc; so[h][1] *= sc; so[h][2] *= sc;
#pragma unroll
                for (int j = 0; j < 8; ++j) {
                    const int cb = kg * 32 + (j >> 1) * 8 + (lane & 3) * 2 + (j & 1);
                    const float p = __expf(lg[j] - nm);
                    stl[h] += p;
                    so[h][0] = fmaf(p, tgs[cb], so[h][0]);
                    so[h][1] = fmaf(p, tgs[128 + cb], so[h][1]);
                    so[h][2] = fmaf(p, tgs[256 + cb], so[h][2]);
                }
                stm[h] = nm;
            }
        }
    }

    // ---- merge across the 4 lanes sharing each row, write partials ----
#pragma unroll
    for (int h = 0; h < 2; ++h) {
        float m = stm[h], l = stl[h];
        float o0 = so[h][0], o1 = so[h][1], o2 = so[h][2];
#pragma unroll
        for (int off = 1; off < 4; off <<= 1) {
            float om = __shfl_xor_sync(0xffffffffu, m,  off, 4);
            float ol = __shfl_xor_sync(0xffffffffu, l,  off, 4);
            float p0 = __shfl_xor_sync(0xffffffffu, o0, off, 4);
            float p1 = __shfl_xor_sync(0xffffffffu, o1, off, 4);
            float p2 = __shfl_xor_sync(0xffffffffu, o2, off, 4);
            const float nm = fmaxf(m, om);
            const float sa = __expf(m - nm), sb = __expf(om - nm);
            l = l * sa + ol * sb;
            o0 = o0 * sa + p0 * sb; o1 = o1 * sa + p1 * sb; o2 = o2 * sa + p2 * sb;
            m = nm;
        }
        if ((lane & 3) == 0) {
            const int n = n0 + qg * 16 + h * 8 + (lane >> 2);
            const size_t pidx = (size_t)(split * 4 + kg) * (BB * NN) + (size_t)b * NN + n;
            g_pm[pidx] = m; g_pl[pidx] = l;
            g_po[3 * pidx + 0] = o0; g_po[3 * pidx + 1] = o1; g_po[3 * pidx + 2] = o2;
        }
    }
}

// ---------------------------------------------------------------------------
__global__ void merge_kernel(float* __restrict__ out_corr)
{
    const int idx = blockIdx.x * 256 + threadIdx.x;
    if (idx >= BB * NN) return;
    const int b = idx >> 12, n = idx & (NN - 1);
    float m = -1e30f;
#pragma unroll
    for (int s = 0; s < 16; ++s) m = fmaxf(m, g_pm[s * BB * NN + idx]);
    float l = 0.f, o0 = 0.f, o1 = 0.f, o2 = 0.f;
#pragma unroll
    for (int s = 0; s < 16; ++s) {
        const size_t p = (size_t)s * BB * NN + idx;
        const float w = __expf(g_pm[p] - m);
        l += g_pl[p] * w;
        o0 += g_po[3 * p + 0] * w; o1 += g_po[3 * p + 1] * w; o2 += g_po[3 * p + 2] * w;
    }
    const float inv = 1.f / l;
    out_corr[((size_t)b * 3 + 0) * NN + n] = o0 * inv;
    out_corr[((size_t)b * 3 + 1) * NN + n] = o1 * inv;
    out_corr[((size_t)b * 3 + 2) * NN + n] = o2 * inv;
}

__global__ void copy_src_kernel(const float* __restrict__ src, float* __restrict__ out)
{
    const int i = blockIdx.x * 256 + threadIdx.x;
    if (i < BB * 3 * NN) out[i] = src[i];
}

// ---------------------------------------------------------------------------
extern "C" void kernel_launch(void* const* d_in, const int* in_sizes, int n_in,
                              void* d_out, int out_size)
{
    const float* src_emb = (const float*)d_in[0];
    const float* tgt_emb = (const float*)d_in[1];
    const float* src     = (const float*)d_in[2];
    const float* tgt     = (const float*)d_in[3];
    const float* Wq      = (const float*)d_in[4];
    const float* bq      = (const float*)d_in[5];
    const float* Wk      = (const float*)d_in[6];
    const float* bk      = (const float*)d_in[7];
    float* out = (float*)d_out;

    const int corr_elems = BB * 3 * NN;
    const bool tuple_out = (out_size >= 2 * corr_elems);
    float* corr_out = tuple_out ? (out + corr_elems) : out;

    dim3 pg(NN / 64, EE / 128, BB);
    proj_kernel<<<pg, 256>>>(src_emb, Wq, bq, 0);
    proj_kernel<<<pg, 256>>>(tgt_emb, Wk, bk, 1);
    kk_kernel<<<BB * MM / 8, 256>>>();

    cudaFuncSetAttribute(attn_kernel, cudaFuncAttributeMaxDynamicSharedMemorySize,
                         SMEM_TOTAL);
    attn_kernel<<<dim3(256, 4), 256, SMEM_TOTAL>>>(tgt);

    merge_kernel<<<(BB * NN + 255) / 256, 256>>>(corr_out);
    if (tuple_out)
        copy_src_kernel<<<(corr_elems + 255) / 256, 256>>>(src, out);
}

// round 9
// speedup vs baseline: 1.1705x; 1.0289x over previous
#include <cuda_runtime.h>
#include <cuda_bf16.h>
#include <stdint.h>

#define BB 2
#define EE 512
#define NN 4096
#define MM 4096

typedef unsigned long long u64;
typedef unsigned int u32;

// ---- scratch ---------------------------------------------------------------
__device__ __nv_bfloat16 g_Qhi[BB * NN * EE];
__device__ __nv_bfloat16 g_Qlo[BB * NN * EE];
__device__ __nv_bfloat16 g_Khi[BB * MM * EE];
__device__ __nv_bfloat16 g_Klo[BB * MM * EE];
__device__ float g_kk[BB * MM];
__device__ float g_pm[32 * BB * NN], g_pl[32 * BB * NN], g_po[32 * BB * NN * 3];

// ---- f32x2 helpers ---------------------------------------------------------
__device__ __forceinline__ u64 pack2(float x) {
    u64 r; asm("mov.b64 %0, {%1, %1};" : "=l"(r) : "f"(x)); return r;
}
__device__ __forceinline__ void fma2(u64& d, u64 a, u64 b) {
    asm("fma.rn.f32x2 %0, %1, %2, %3;" : "=l"(d) : "l"(a), "l"(b), "l"(d));
}
__device__ __forceinline__ float2 unpack2(u64 v) {
    float2 f; asm("mov.b64 {%0, %1}, %2;" : "=f"(f.x), "=f"(f.y) : "l"(v)); return f;
}

// ---- PTX helpers (portable, no 'a'-features) -------------------------------
__device__ __forceinline__ u32 smem_u32(const void* p) {
    u32 a;
    asm("{ .reg .u64 t; cvta.to.shared.u64 t, %1; cvt.u32.u64 %0, t; }" : "=r"(a) : "l"(p));
    return a;
}
__device__ __forceinline__ void cp16(u32 dst, const void* src) {
    asm volatile("cp.async.cg.shared.global [%0], [%1], 16;" :: "r"(dst), "l"(src) : "memory");
}
#define CP_COMMIT() asm volatile("cp.async.commit_group;" ::: "memory")
#define CP_WAIT0()  asm volatile("cp.async.wait_group 0;" ::: "memory")
#define CP_WAIT1()  asm volatile("cp.async.wait_group 1;" ::: "memory")

__device__ __forceinline__ void ldsm4(u32* r, u32 a) {
    asm volatile("ldmatrix.sync.aligned.m8n8.x4.shared.b16 {%0,%1,%2,%3}, [%4];"
                 : "=r"(r[0]), "=r"(r[1]), "=r"(r[2]), "=r"(r[3]) : "r"(a));
}
__device__ __forceinline__ void mma16816(float* c, const u32* a, const u32* b) {
    asm volatile(
        "mma.sync.aligned.m16n8k16.row.col.f32.bf16.bf16.f32 "
        "{%0,%1,%2,%3}, {%4,%5,%6,%7}, {%8,%9}, {%0,%1,%2,%3};"
        : "+f"(c[0]), "+f"(c[1]), "+f"(c[2]), "+f"(c[3])
        : "r"(a[0]), "r"(a[1]), "r"(a[2]), "r"(a[3]), "r"(b[0]), "r"(b[1]));
}
__device__ __forceinline__ u32 bf2_u32(float a, float b) {
    __nv_bfloat162 t = __floats2bfloat162_rn(a, b);
    return *reinterpret_cast<u32*>(&t);
}

// ---------------------------------------------------------------------------
// Projection -> bf16 hi/lo [b][n][e]
// ---------------------------------------------------------------------------
__global__ __launch_bounds__(256) void proj_kernel(
    const float* __restrict__ X, const float* __restrict__ W,
    const float* __restrict__ bias, int which)
{
    __nv_bfloat16* __restrict__ Yh = which ? g_Khi : g_Qhi;
    __nv_bfloat16* __restrict__ Yl = which ? g_Klo : g_Qlo;
    __shared__ float Xs[32][64];
    __shared__ float Ws[32][128];

    const int tid = threadIdx.x;
    const int tx = tid & 15, ty = tid >> 4;
    const int n0 = blockIdx.x * 64, f0 = blockIdx.y * 128, b = blockIdx.z;

    u64 acc[4][4];
#pragma unroll
    for (int i = 0; i < 4; ++i)
#pragma unroll
        for (int j = 0; j < 4; ++j) acc[i][j] = 0ull;

    const float* Xb = X + (size_t)b * EE * NN;
    for (int e0 = 0; e0 < EE; e0 += 32) {
        {
            const int r = tid >> 3, c = (tid & 7) * 8;
            const float4* s4 = (const float4*)(Xb + (size_t)(e0 + r) * NN + n0 + c);
            float4 v0 = s4[0], v1 = s4[1];
            *(float4*)&Xs[r][c] = v0; *(float4*)&Xs[r][c + 4] = v1;
        }
        {
            const int f = tid >> 1, eo = (tid & 1) * 16;
            const float4* w4 = (const float4*)(W + (size_t)(f0 + f) * EE + e0 + eo);
#pragma unroll
            for (int k = 0; k < 4; ++k) {
                float4 v = w4[k];
                Ws[eo + 4*k + 0][f] = v.x; Ws[eo + 4*k + 1][f] = v.y;
                Ws[eo + 4*k + 2][f] = v.z; Ws[eo + 4*k + 3][f] = v.w;
            }
        }
        __syncthreads();
#pragma unroll 8
        for (int e = 0; e < 32; ++e) {
            float4 a = *(const float4*)&Xs[e][ty * 4];
            ulonglong2 b0 = *(const ulonglong2*)&Ws[e][tx * 4];
            ulonglong2 b1 = *(const ulonglong2*)&Ws[e][64 + tx * 4];
            u64 ap;
            ap = pack2(a.x);
            fma2(acc[0][0], ap, b0.x); fma2(acc[0][1], ap, b0.y);
            fma2(acc[0][2], ap, b1.x); fma2(acc[0][3], ap, b1.y);
            ap = pack2(a.y);
            fma2(acc[1][0], ap, b0.x); fma2(acc[1][1], ap, b0.y);
            fma2(acc[1][2], ap, b1.x); fma2(acc[1][3], ap, b1.y);
            ap = pack2(a.z);
            fma2(acc[2][0], ap, b0.x); fma2(acc[2][1], ap, b0.y);
            fma2(acc[2][2], ap, b1.x); fma2(acc[2][3], ap, b1.y);
            ap = pack2(a.w);
            fma2(acc[3][0], ap, b0.x); fma2(acc[3][1], ap, b0.y);
            fma2(acc[3][2], ap, b1.x); fma2(acc[3][3], ap, b1.y);
        }
        __syncthreads();
    }

    float4 bs0 = *(const float4*)(bias + f0 + tx * 4);
    float4 bs1 = *(const float4*)(bias + f0 + 64 + tx * 4);
    float bv[8] = {bs0.x, bs0.y, bs0.z, bs0.w, bs1.x, bs1.y, bs1.z, bs1.w};
#pragma unroll
    for (int i = 0; i < 4; ++i) {
        float y[8]; float2 p;
        p = unpack2(acc[i][0]); y[0] = p.x + bv[0]; y[1] = p.y + bv[1];
        p = unpack2(acc[i][1]); y[2] = p.x + bv[2]; y[3] = p.y + bv[3];
        p = unpack2(acc[i][2]); y[4] = p.x + bv[4]; y[5] = p.y + bv[5];
        p = unpack2(acc[i][3]); y[6] = p.x + bv[6]; y[7] = p.y + bv[7];
        float hf[8], lf[8];
#pragma unroll
        for (int j = 0; j < 8; ++j) {
            __nv_bfloat16 h = __float2bfloat16_rn(y[j]);
            hf[j] = __bfloat162float(h);
            lf[j] = y[j] - hf[j];
        }
        const size_t rowo = ((size_t)b * NN + n0 + ty * 4 + i) * EE;
#pragma unroll
        for (int g = 0; g < 2; ++g) {
            uint2 ph, pl;
            ph.x = bf2_u32(hf[g*4+0], hf[g*4+1]); ph.y = bf2_u32(hf[g*4+2], hf[g*4+3]);
            pl.x = bf2_u32(lf[g*4+0], lf[g*4+1]); pl.y = bf2_u32(lf[g*4+2], lf[g*4+3]);
            const size_t off = rowo + f0 + g * 64 + tx * 4;
            *(uint2*)(Yh + off) = ph;
            *(uint2*)(Yl + off) = pl;
        }
    }
}

// ---------------------------------------------------------------------------
__global__ __launch_bounds__(256) void kk_kernel()
{
    const int row = blockIdx.x * 8 + (threadIdx.x >> 5);
    const int lane = threadIdx.x & 31;
    const uint4* h4 = (const uint4*)(g_Khi + (size_t)row * EE);
    const uint4* l4 = (const uint4*)(g_Klo + (size_t)row * EE);
    float s = 0.f;
#pragma unroll
    for (int it = 0; it < 2; ++it) {
        uint4 h = h4[lane + it * 32], l = l4[lane + it * 32];
        const __nv_bfloat162* hp = (const __nv_bfloat162*)&h;
        const __nv_bfloat162* lp = (const __nv_bfloat162*)&l;
#pragma unroll
        for (int k = 0; k < 4; ++k) {
            float2 fh = __bfloat1622float2(hp[k]);
            float2 fl = __bfloat1622float2(lp[k]);
            float x = fh.x + fl.x, y = fh.y + fl.y;
            s = fmaf(x, x, fmaf(y, y, s));
        }
    }
#pragma unroll
    for (int off = 16; off; off >>= 1) s += __shfl_xor_sync(0xffffffffu, s, off);
    if (lane == 0) g_kk[row] = s;
}

// ---------------------------------------------------------------------------
// mma.sync attention — warp-autonomous pipelines, zero CTA barriers in mainloop.
// grid (256, 4): b = bx>>7, q-tile = bx&127 (32 rows), by = m-split (1024 keys).
// 8 warps; warp w owns private 16-key slice of each 128-key tile, covers all 32 q.
// ---------------------------------------------------------------------------
#define QPITCH 1040
#define SM_QH 0
#define SM_QL 33280
#define SM_K  66560          /* [2 stages][hi/lo][128 keys][80B] */
#define KPITCH 80
#define KLO_OFF 10240
#define STAGE 20480
#define SMEM_TOTAL 107520

__global__ __launch_bounds__(256, 2) void attn_kernel(const float* __restrict__ tgt)
{
    extern __shared__ char smraw[];
    const u32 S = smem_u32(smraw);
    const int tid = threadIdx.x, kg = tid >> 5, lane = tid & 31;
    const int b = blockIdx.x >> 7, n0 = (blockIdx.x & 127) * 32;
    const int mbase = blockIdx.y * 1024;

    // ---- Q tile fill (once): 32 rows x 512 e, hi+lo; one barrier total ----
    {
        const char* qh = (const char*)(g_Qhi + (size_t)(b * NN + n0) * EE);
        const char* ql = (const char*)(g_Qlo + (size_t)(b * NN + n0) * EE);
#pragma unroll
        for (int it = 0; it < 8; ++it) {
            const int i = tid + it * 256;
            const int row = i >> 6, g = (i & 63) * 16;
            cp16(S + SM_QH + row * QPITCH + g, qh + row * 1024 + g);
            cp16(S + SM_QL + row * QPITCH + g, ql + row * 1024 + g);
        }
        CP_COMMIT(); CP_WAIT0();
        __syncthreads();
    }

    // lane-constant ldmatrix offsets
    const int laneQrow = (lane & 7) + ((lane >> 3) & 1) * 8;
    const int laneQcolB = (lane >> 4) * 16;
    const int laneKn = (lane & 7) + ((lane >> 4) & 1) * 8;
    const int laneKeB = ((lane >> 3) & 1) * 16;
    u32 qoff[2];
    qoff[0] = (u32)(laneQrow * QPITCH + laneQcolB);
    qoff[1] = qoff[0] + 16 * QPITCH;
    const u32 koff = (u32)((kg * 16 + laneKn) * KPITCH + laneKeB);

    // fill addressing: lane -> key = lane>>1, byte-half gb = (lane&1)*32
    const u32 fko = (u32)((kg * 16 + (lane >> 1)) * KPITCH + (lane & 1) * 32);
    const char* src_h = (const char*)g_Khi
        + ((size_t)(b * MM + mbase + kg * 16 + (lane >> 1))) * 1024 + (lane & 1) * 32;
    const char* src_l = (const char*)g_Klo
        + ((size_t)(b * MM + mbase + kg * 16 + (lane >> 1))) * 1024 + (lane & 1) * 32;

    const float* kkb = g_kk + b * MM + mbase;
    const float* tgtb = tgt + (size_t)b * 3 * MM + mbase;

    float stm[4], stl[4], so[4][3];
#pragma unroll
    for (int r = 0; r < 4; ++r) {
        stm[r] = -1e30f; stl[r] = 0.f;
        so[r][0] = so[r][1] = so[r][2] = 0.f;
    }

    float acc[2][2][4];
#pragma unroll
    for (int mt = 0; mt < 2; ++mt)
#pragma unroll
        for (int nt = 0; nt < 2; ++nt)
#pragma unroll
            for (int j = 0; j < 4; ++j) acc[mt][nt][j] = 0.f;

    // prologue: fill chunk 0
    {
        const size_t go = 0;
        cp16(S + SM_K + fko,             src_h + go);
        cp16(S + SM_K + fko + 16,        src_h + go + 16);
        cp16(S + SM_K + KLO_OFF + fko,      src_l + go);
        cp16(S + SM_K + KLO_OFF + fko + 16, src_l + go + 16);
        CP_COMMIT();
    }

    for (int cc = 0; cc < 128; ++cc) {
        // issue fill(cc+1) before waiting on fill(cc); wait leaves it in flight
        if (cc < 127) {
            const int nc = cc + 1;
            const u32 dst = S + SM_K + (u32)(nc & 1) * STAGE + fko;
            const size_t go = (size_t)(nc >> 4) * 131072 + (size_t)(nc & 15) * 64;
            cp16(dst,                src_h + go);
            cp16(dst + 16,           src_h + go + 16);
            cp16(dst + KLO_OFF,      src_l + go);
            cp16(dst + KLO_OFF + 16, src_l + go + 16);
            CP_COMMIT();
            CP_WAIT1();
        } else {
            CP_WAIT0();
        }
        __syncwarp();

        const u32 KB = S + SM_K + (u32)(cc & 1) * STAGE;
        const u32 chB = (u32)((cc & 15) * 64);
#pragma unroll
        for (int s = 0; s < 2; ++s) {
            const u32 qeB = chB + (u32)(s * 32);
            const u32 keB = (u32)(s * 32);
            u32 ah[2][4], al[2][4], bh[4], bl[4];
#pragma unroll
            for (int mt = 0; mt < 2; ++mt) {
                ldsm4(ah[mt], S + SM_QH + qoff[mt] + qeB);
                ldsm4(al[mt], S + SM_QL + qoff[mt] + qeB);
            }
            ldsm4(bh, KB + koff + keB);
            ldsm4(bl, KB + KLO_OFF + koff + keB);
#pragma unroll
            for (int mt = 0; mt < 2; ++mt) {
                mma16816(acc[mt][0], ah[mt], &bh[0]);
                mma16816(acc[mt][0], ah[mt], &bl[0]);
                mma16816(acc[mt][0], al[mt], &bh[0]);
                mma16816(acc[mt][1], ah[mt], &bh[2]);
                mma16816(acc[mt][1], ah[mt], &bl[2]);
                mma16816(acc[mt][1], al[mt], &bh[2]);
            }
        }

        if ((cc & 15) == 15) {
            // ---- per-tile epilogue: online softmax, direct global kk/tgt ----
            const int m0 = (cc >> 4) * 128;
            const int c0 = kg * 16 + (lane & 3) * 2;
            const float kk0 = __ldg(kkb + m0 + c0);
            const float kk1 = __ldg(kkb + m0 + c0 + 1);
            const float kk2 = __ldg(kkb + m0 + c0 + 8);
            const float kk3 = __ldg(kkb + m0 + c0 + 9);
#pragma unroll
            for (int mt = 0; mt < 2; ++mt)
#pragma unroll
                for (int h = 0; h < 2; ++h) {
                    const int r = mt * 2 + h;
                    float lg[4];
                    lg[0] = fmaf(2.f, acc[mt][0][h*2+0], -kk0);
                    lg[1] = fmaf(2.f, acc[mt][0][h*2+1], -kk1);
                    lg[2] = fmaf(2.f, acc[mt][1][h*2+0], -kk2);
                    lg[3] = fmaf(2.f, acc[mt][1][h*2+1], -kk3);
                    const float vmax = fmaxf(fmaxf(lg[0], lg[1]), fmaxf(lg[2], lg[3]));
                    if (vmax >= stm[r] - 30.f) {   // skip adds < 3e-9 rel error
                        const float nm = fmaxf(stm[r], vmax);
                        const float sc = __expf(stm[r] - nm);
                        stl[r] *= sc; so[r][0] *= sc; so[r][1] *= sc; so[r][2] *= sc;
                        const float p0 = __expf(lg[0] - nm);
                        const float p1 = __expf(lg[1] - nm);
                        const float p2 = __expf(lg[2] - nm);
                        const float p3 = __expf(lg[3] - nm);
                        stl[r] += (p0 + p1) + (p2 + p3);
#pragma unroll
                        for (int d = 0; d < 3; ++d) {
                            const float* tp = tgtb + d * MM + m0 + c0;
                            so[r][d] += p0 * __ldg(tp) + p1 * __ldg(tp + 1)
                                      + p2 * __ldg(tp + 8) + p3 * __ldg(tp + 9);
                        }
                        stm[r] = nm;
                    }
                    // reset acc for next tile
                    acc[mt][0][h*2+0] = 0.f; acc[mt][0][h*2+1] = 0.f;
                    acc[mt][1][h*2+0] = 0.f; acc[mt][1][h*2+1] = 0.f;
                }
        }
    }

    // ---- merge across the 4 lanes sharing each row, write partials ----
#pragma unroll
    for (int mt = 0; mt < 2; ++mt)
#pragma unroll
        for (int h = 0; h < 2; ++h) {
            const int r = mt * 2 + h;
            float m = stm[r], l = stl[r];
            float o0 = so[r][0], o1 = so[r][1], o2 = so[r][2];
#pragma unroll
            for (int off = 1; off < 4; off <<= 1) {
                float om = __shfl_xor_sync(0xffffffffu, m,  off, 4);
                float ol = __shfl_xor_sync(0xffffffffu, l,  off, 4);
                float p0 = __shfl_xor_sync(0xffffffffu, o0, off, 4);
                float p1 = __shfl_xor_sync(0xffffffffu, o1, off, 4);
                float p2 = __shfl_xor_sync(0xffffffffu, o2, off, 4);
                const float nm = fmaxf(m, om);
                const float sa = __expf(m - nm), sb = __expf(om - nm);
                l = l * sa + ol * sb;
                o0 = o0 * sa + p0 * sb; o1 = o1 * sa + p1 * sb; o2 = o2 * sa + p2 * sb;
                m = nm;
            }
            if ((lane & 3) == 0) {
                const int n = n0 + mt * 16 + h * 8 + (lane >> 2);
                const size_t pidx = (size_t)(blockIdx.y * 8 + kg) * (BB * NN)
                                  + (size_t)b * NN + n;
                g_pm[pidx] = m; g_pl[pidx] = l;
                g_po[3 * pidx + 0] = o0; g_po[3 * pidx + 1] = o1; g_po[3 * pidx + 2] = o2;
            }
        }
}

// ---------------------------------------------------------------------------
__global__ void merge_kernel(float* __restrict__ out_corr)
{
    const int idx = blockIdx.x * 256 + threadIdx.x;
    if (idx >= BB * NN) return;
    const int b = idx >> 12, n = idx & (NN - 1);
    float m = -1e30f;
#pragma unroll
    for (int s = 0; s < 32; ++s) m = fmaxf(m, g_pm[s * BB * NN + idx]);
    float l = 0.f, o0 = 0.f, o1 = 0.f, o2 = 0.f;
#pragma unroll
    for (int s = 0; s < 32; ++s) {
        const size_t p = (size_t)s * BB * NN + idx;
        const float w = __expf(g_pm[p] - m);
        l += g_pl[p] * w;
        o0 += g_po[3 * p + 0] * w; o1 += g_po[3 * p + 1] * w; o2 += g_po[3 * p + 2] * w;
    }
    const float inv = 1.f / l;
    out_corr[((size_t)b * 3 + 0) * NN + n] = o0 * inv;
    out_corr[((size_t)b * 3 + 1) * NN + n] = o1 * inv;
    out_corr[((size_t)b * 3 + 2) * NN + n] = o2 * inv;
}

__global__ void copy_src_kernel(const float* __restrict__ src, float* __restrict__ out)
{
    const int i = blockIdx.x * 256 + threadIdx.x;
    if (i < BB * 3 * NN) out[i] = src[i];
}

// ---------------------------------------------------------------------------
extern "C" void kernel_launch(void* const* d_in, const int* in_sizes, int n_in,
                              void* d_out, int out_size)
{
    const float* src_emb = (const float*)d_in[0];
    const float* tgt_emb = (const float*)d_in[1];
    const float* src     = (const float*)d_in[2];
    const float* tgt     = (const float*)d_in[3];
    const float* Wq      = (const float*)d_in[4];
    const float* bq      = (const float*)d_in[5];
    const float* Wk      = (const float*)d_in[6];
    const float* bk      = (const float*)d_in[7];
    float* out = (float*)d_out;

    const int corr_elems = BB * 3 * NN;
    const bool tuple_out = (out_size >= 2 * corr_elems);
    float* corr_out = tuple_out ? (out + corr_elems) : out;

    dim3 pg(NN / 64, EE / 128, BB);
    proj_kernel<<<pg, 256>>>(src_emb, Wq, bq, 0);
    proj_kernel<<<pg, 256>>>(tgt_emb, Wk, bk, 1);
    kk_kernel<<<BB * MM / 8, 256>>>();

    cudaFuncSetAttribute(attn_kernel, cudaFuncAttributeMaxDynamicSharedMemorySize,
                         SMEM_TOTAL);
    attn_kernel<<<dim3(256, 4), 256, SMEM_TOTAL>>>(tgt);

    merge_kernel<<<(BB * NN + 255) / 256, 256>>>(corr_out);
    if (tuple_out)
        copy_src_kernel<<<(corr_elems + 255) / 256, 256>>>(src, out);
}

// round 10
// speedup vs baseline: 1.4673x; 1.2535x over previous
#include <cuda_runtime.h>
#include <cuda_bf16.h>
#include <stdint.h>

#define BB 2
#define EE 512
#define NN 4096
#define MM 4096

typedef unsigned long long u64;
typedef unsigned int u32;

// ---- scratch ---------------------------------------------------------------
__device__ __nv_bfloat16 g_Qhi[BB * NN * EE], g_Qlo[BB * NN * EE];
__device__ __nv_bfloat16 g_Khi[BB * MM * EE], g_Klo[BB * MM * EE];
__device__ __nv_bfloat16 g_XQhi[BB * NN * EE], g_XQlo[BB * NN * EE];
__device__ __nv_bfloat16 g_XKhi[BB * MM * EE], g_XKlo[BB * MM * EE];
__device__ __nv_bfloat16 g_Whi[2 * EE * EE], g_Wlo[2 * EE * EE];
__device__ float g_kk[BB * MM];
__device__ float g_pm[32 * BB * NN], g_pl[32 * BB * NN], g_po[32 * BB * NN * 3];

// ---- PTX helpers (portable, no 'a'-features) -------------------------------
__device__ __forceinline__ u32 smem_u32(const void* p) {
    u32 a;
    asm("{ .reg .u64 t; cvta.to.shared.u64 t, %1; cvt.u32.u64 %0, t; }" : "=r"(a) : "l"(p));
    return a;
}
__device__ __forceinline__ void cp16(u32 dst, const void* src) {
    asm volatile("cp.async.cg.shared.global [%0], [%1], 16;" :: "r"(dst), "l"(src) : "memory");
}
#define CP_COMMIT() asm volatile("cp.async.commit_group;" ::: "memory")
#define CP_WAIT0()  asm volatile("cp.async.wait_group 0;" ::: "memory")
#define CP_WAIT1()  asm volatile("cp.async.wait_group 1;" ::: "memory")

__device__ __forceinline__ void ldsm4(u32* r, u32 a) {
    asm volatile("ldmatrix.sync.aligned.m8n8.x4.shared.b16 {%0,%1,%2,%3}, [%4];"
                 : "=r"(r[0]), "=r"(r[1]), "=r"(r[2]), "=r"(r[3]) : "r"(a));
}
__device__ __forceinline__ void mma16816(float* c, const u32* a, const u32* b) {
    asm volatile(
        "mma.sync.aligned.m16n8k16.row.col.f32.bf16.bf16.f32 "
        "{%0,%1,%2,%3}, {%4,%5,%6,%7}, {%8,%9}, {%0,%1,%2,%3};"
        : "+f"(c[0]), "+f"(c[1]), "+f"(c[2]), "+f"(c[3])
        : "r"(a[0]), "r"(a[1]), "r"(a[2]), "r"(a[3]), "r"(b[0]), "r"(b[1]));
}
__device__ __forceinline__ u32 packbf(__nv_bfloat16 a, __nv_bfloat16 b) {
    __nv_bfloat162 t; t.x = a; t.y = b;
    return *reinterpret_cast<u32*>(&t);
}

// ---------------------------------------------------------------------------
// split W: [f][e] fp32 -> bf16 hi/lo, slot = 0 (Wq) / 1 (Wk)
// ---------------------------------------------------------------------------
__global__ __launch_bounds__(256) void splitW_kernel(const float* __restrict__ W, int slot)
{
    const int i = (blockIdx.x * 256 + threadIdx.x) * 4;
    float4 v = *(const float4*)(W + i);
    float x[4] = {v.x, v.y, v.z, v.w};
    __nv_bfloat16 h[4]; float l[4];
#pragma unroll
    for (int k = 0; k < 4; ++k) {
        h[k] = __float2bfloat16_rn(x[k]);
        l[k] = x[k] - __bfloat162float(h[k]);
    }
    uint2 ph, pl;
    ph.x = packbf(h[0], h[1]); ph.y = packbf(h[2], h[3]);
    pl.x = packbf(__float2bfloat16_rn(l[0]), __float2bfloat16_rn(l[1]));
    pl.y = packbf(__float2bfloat16_rn(l[2]), __float2bfloat16_rn(l[3]));
    const size_t off = (size_t)slot * EE * EE + i;
    *(uint2*)(g_Whi + off) = ph;
    *(uint2*)(g_Wlo + off) = pl;
}

// ---------------------------------------------------------------------------
// split+transpose X: [b][e][n] fp32 -> bf16 hi/lo [b][n][e]
// ---------------------------------------------------------------------------
__global__ __launch_bounds__(256) void splitX_kernel(const float* __restrict__ X, int which)
{
    __nv_bfloat16* __restrict__ Yh = which ? g_XKhi : g_XQhi;
    __nv_bfloat16* __restrict__ Yl = which ? g_XKlo : g_XQlo;
    __shared__ float tile[64][65];
    const int tid = threadIdx.x;
    const int n0 = blockIdx.x * 64, e0 = blockIdx.y * 64, b = blockIdx.z;
    const float* Xb = X + (size_t)b * EE * NN;

    const int lr = tid >> 4, n4 = tid & 15;
#pragma unroll
    for (int it = 0; it < 4; ++it) {
        const int e = lr + it * 16;
        float4 v = *(const float4*)(Xb + (size_t)(e0 + e) * NN + n0 + n4 * 4);
        tile[e][n4*4+0] = v.x; tile[e][n4*4+1] = v.y;
        tile[e][n4*4+2] = v.z; tile[e][n4*4+3] = v.w;
    }
    __syncthreads();

    const int n = tid >> 2, et = tid & 3;
    u32 hw[8], lw[8];
#pragma unroll
    for (int k = 0; k < 8; ++k) {
        const float a = tile[et*16 + 2*k][n], c = tile[et*16 + 2*k + 1][n];
        __nv_bfloat16 ha = __float2bfloat16_rn(a), hc = __float2bfloat16_rn(c);
        hw[k] = packbf(ha, hc);
        lw[k] = packbf(__float2bfloat16_rn(a - __bfloat162float(ha)),
                       __float2bfloat16_rn(c - __bfloat162float(hc)));
    }
    const size_t base = ((size_t)b * NN + n0 + n) * EE + e0 + et * 16;
    *(uint4*)(Yh + base)     = *(uint4*)(hw);
    *(uint4*)(Yh + base + 8) = *(uint4*)(hw + 4);
    *(uint4*)(Yl + base)     = *(uint4*)(lw);
    *(uint4*)(Yl + base + 8) = *(uint4*)(lw + 4);
}

// ---------------------------------------------------------------------------
// proj via mma: out[n][f] = sum_e X[n][e]*W[f][e] + bias[f], 3-term bf16 split.
// Clone of attn mainloop: CTA 32n x 128f, 8 warps, warp owns 16-f slice.
// grid (256, 4): b = bx>>7, n-tile = bx&127, f-tile = by.
// ---------------------------------------------------------------------------
#define QPITCH 1040
#define SM_QH 0
#define SM_QL 33280
#define SM_K  66560
#define KPITCH 80
#define KLO_OFF 10240
#define STAGE 20480
#define SMEM_TOTAL 107520

__global__ __launch_bounds__(256, 2) void projmma_kernel(const float* __restrict__ bias,
                                                         int which)
{
    extern __shared__ char smraw[];
    const u32 S = smem_u32(smraw);
    const int tid = threadIdx.x, kg = tid >> 5, lane = tid & 31;
    const int b = blockIdx.x >> 7, n0 = (blockIdx.x & 127) * 32;
    const int f0 = blockIdx.y * 128;
    const __nv_bfloat16* Axh = which ? g_XKhi : g_XQhi;
    const __nv_bfloat16* Axl = which ? g_XKlo : g_XQlo;
    __nv_bfloat16* Oh = which ? g_Khi : g_Qhi;
    __nv_bfloat16* Ol = which ? g_Klo : g_Qlo;
    const char* Wh = (const char*)(g_Whi + (size_t)which * EE * EE);
    const char* Wl = (const char*)(g_Wlo + (size_t)which * EE * EE);

    // A tile fill (32 rows x 512 e, hi+lo)
    {
        const char* ah = (const char*)(Axh + (size_t)(b * NN + n0) * EE);
        const char* al = (const char*)(Axl + (size_t)(b * NN + n0) * EE);
#pragma unroll
        for (int it = 0; it < 8; ++it) {
            const int i = tid + it * 256;
            const int row = i >> 6, g = (i & 63) * 16;
            cp16(S + SM_QH + row * QPITCH + g, ah + row * 1024 + g);
            cp16(S + SM_QL + row * QPITCH + g, al + row * 1024 + g);
        }
        CP_COMMIT(); CP_WAIT0();
        __syncthreads();
    }

    const int laneQrow = (lane & 7) + ((lane >> 3) & 1) * 8;
    const int laneQcolB = (lane >> 4) * 16;
    const int laneKn = (lane & 7) + ((lane >> 4) & 1) * 8;
    const int laneKeB = ((lane >> 3) & 1) * 16;
    u32 qoff[2];
    qoff[0] = (u32)(laneQrow * QPITCH + laneQcolB);
    qoff[1] = qoff[0] + 16 * QPITCH;
    const u32 koff = (u32)((kg * 16 + laneKn) * KPITCH + laneKeB);

    const u32 fko = (u32)((kg * 16 + (lane >> 1)) * KPITCH + (lane & 1) * 32);
    const char* sWh = Wh + (size_t)(f0 + kg * 16 + (lane >> 1)) * 1024 + (lane & 1) * 32;
    const char* sWl = Wl + (size_t)(f0 + kg * 16 + (lane >> 1)) * 1024 + (lane & 1) * 32;

    float acc[2][2][4];
#pragma unroll
    for (int mt = 0; mt < 2; ++mt)
#pragma unroll
        for (int nt = 0; nt < 2; ++nt)
#pragma unroll
            for (int j = 0; j < 4; ++j) acc[mt][nt][j] = 0.f;

    cp16(S + SM_K + fko,                sWh);
    cp16(S + SM_K + fko + 16,           sWh + 16);
    cp16(S + SM_K + KLO_OFF + fko,      sWl);
    cp16(S + SM_K + KLO_OFF + fko + 16, sWl + 16);
    CP_COMMIT();

    for (int cc = 0; cc < 16; ++cc) {
        if (cc < 15) {
            const int nc = cc + 1;
            const u32 dst = S + SM_K + (u32)(nc & 1) * STAGE + fko;
            const size_t go = (size_t)nc * 64;
            cp16(dst,                sWh + go);
            cp16(dst + 16,           sWh + go + 16);
            cp16(dst + KLO_OFF,      sWl + go);
            cp16(dst + KLO_OFF + 16, sWl + go + 16);
            CP_COMMIT();
            CP_WAIT1();
        } else {
            CP_WAIT0();
        }
        __syncwarp();
        const u32 KB = S + SM_K + (u32)(cc & 1) * STAGE;
        const u32 chB = (u32)(cc * 64);
#pragma unroll
        for (int s = 0; s < 2; ++s) {
            const u32 qeB = chB + (u32)(s * 32);
            const u32 keB = (u32)(s * 32);
            u32 ah[2][4], al[2][4], bh[4], bl[4];
#pragma unroll
            for (int mt = 0; mt < 2; ++mt) {
                ldsm4(ah[mt], S + SM_QH + qoff[mt] + qeB);
                ldsm4(al[mt], S + SM_QL + qoff[mt] + qeB);
            }
            ldsm4(bh, KB + koff + keB);
            ldsm4(bl, KB + KLO_OFF + koff + keB);
#pragma unroll
            for (int mt = 0; mt < 2; ++mt) {
                mma16816(acc[mt][0], ah[mt], &bh[0]);
                mma16816(acc[mt][0], ah[mt], &bl[0]);
                mma16816(acc[mt][0], al[mt], &bh[0]);
                mma16816(acc[mt][1], ah[mt], &bh[2]);
                mma16816(acc[mt][1], ah[mt], &bl[2]);
                mma16816(acc[mt][1], al[mt], &bh[2]);
            }
        }
    }

    // ---- epilogue: bias, hi/lo split, smem staging, coalesced store ----
    __syncthreads();   // all warps done with B stages; reuse as staging
    float bias2[2][2];
#pragma unroll
    for (int nt = 0; nt < 2; ++nt)
#pragma unroll
        for (int j = 0; j < 2; ++j)
            bias2[nt][j] = __ldg(bias + f0 + kg * 16 + nt * 8 + (lane & 3) * 2 + j);
    __nv_bfloat16* sh = (__nv_bfloat16*)(smraw + SM_K);
    __nv_bfloat16* sl = (__nv_bfloat16*)(smraw + SM_K + 8192);
#pragma unroll
    for (int mt = 0; mt < 2; ++mt)
#pragma unroll
        for (int nt = 0; nt < 2; ++nt)
#pragma unroll
            for (int c = 0; c < 4; ++c) {
                const int row = mt * 16 + (lane >> 2) + (c >> 1) * 8;
                const int col = kg * 16 + nt * 8 + (lane & 3) * 2 + (c & 1);
                const float q = acc[mt][nt][c] + bias2[nt][c & 1];
                const __nv_bfloat16 h = __float2bfloat16_rn(q);
                sh[row * 128 + col] = h;
                sl[row * 128 + col] = __float2bfloat16_rn(q - __bfloat162float(h));
            }
    __syncthreads();
    {
        const int row = tid >> 3, seg = tid & 7;
        const size_t gbase = ((size_t)(b * NN + n0 + row)) * EE + f0 + seg * 16;
        const int sbase = row * 128 + seg * 16;
        *(uint4*)(Oh + gbase)     = *(uint4*)(sh + sbase);
        *(uint4*)(Oh + gbase + 8) = *(uint4*)(sh + sbase + 8);
        *(uint4*)(Ol + gbase)     = *(uint4*)(sl + sbase);
        *(uint4*)(Ol + gbase + 8) = *(uint4*)(sl + sbase + 8);
    }
}

// ---------------------------------------------------------------------------
__global__ __launch_bounds__(256) void kk_kernel()
{
    const int row = blockIdx.x * 8 + (threadIdx.x >> 5);
    const int lane = threadIdx.x & 31;
    const uint4* h4 = (const uint4*)(g_Khi + (size_t)row * EE);
    const uint4* l4 = (const uint4*)(g_Klo + (size_t)row * EE);
    float s = 0.f;
#pragma unroll
    for (int it = 0; it < 2; ++it) {
        uint4 h = h4[lane + it * 32], l = l4[lane + it * 32];
        const __nv_bfloat162* hp = (const __nv_bfloat162*)&h;
        const __nv_bfloat162* lp = (const __nv_bfloat162*)&l;
#pragma unroll
        for (int k = 0; k < 4; ++k) {
            float2 fh = __bfloat1622float2(hp[k]);
            float2 fl = __bfloat1622float2(lp[k]);
            float x = fh.x + fl.x, y = fh.y + fl.y;
            s = fmaf(x, x, fmaf(y, y, s));
        }
    }
#pragma unroll
    for (int off = 16; off; off >>= 1) s += __shfl_xor_sync(0xffffffffu, s, off);
    if (lane == 0) g_kk[row] = s;
}

// ---------------------------------------------------------------------------
// mma.sync attention — warp-autonomous pipelines (unchanged from round 9).
// ---------------------------------------------------------------------------
__global__ __launch_bounds__(256, 2) void attn_kernel(const float* __restrict__ tgt)
{
    extern __shared__ char smraw[];
    const u32 S = smem_u32(smraw);
    const int tid = threadIdx.x, kg = tid >> 5, lane = tid & 31;
    const int b = blockIdx.x >> 7, n0 = (blockIdx.x & 127) * 32;
    const int mbase = blockIdx.y * 1024;

    {
        const char* qh = (const char*)(g_Qhi + (size_t)(b * NN + n0) * EE);
        const char* ql = (const char*)(g_Qlo + (size_t)(b * NN + n0) * EE);
#pragma unroll
        for (int it = 0; it < 8; ++it) {
            const int i = tid + it * 256;
            const int row = i >> 6, g = (i & 63) * 16;
            cp16(S + SM_QH + row * QPITCH + g, qh + row * 1024 + g);
            cp16(S + SM_QL + row * QPITCH + g, ql + row * 1024 + g);
        }
        CP_COMMIT(); CP_WAIT0();
        __syncthreads();
    }

    const int laneQrow = (lane & 7) + ((lane >> 3) & 1) * 8;
    const int laneQcolB = (lane >> 4) * 16;
    const int laneKn = (lane & 7) + ((lane >> 4) & 1) * 8;
    const int laneKeB = ((lane >> 3) & 1) * 16;
    u32 qoff[2];
    qoff[0] = (u32)(laneQrow * QPITCH + laneQcolB);
    qoff[1] = qoff[0] + 16 * QPITCH;
    const u32 koff = (u32)((kg * 16 + laneKn) * KPITCH + laneKeB);

    const u32 fko = (u32)((kg * 16 + (lane >> 1)) * KPITCH + (lane & 1) * 32);
    const char* src_h = (const char*)g_Khi
        + ((size_t)(b * MM + mbase + kg * 16 + (lane >> 1))) * 1024 + (lane & 1) * 32;
    const char* src_l = (const char*)g_Klo
        + ((size_t)(b * MM + mbase + kg * 16 + (lane >> 1))) * 1024 + (lane & 1) * 32;

    const float* kkb = g_kk + b * MM + mbase;
    const float* tgtb = tgt + (size_t)b * 3 * MM + mbase;

    float stm[4], stl[4], so[4][3];
#pragma unroll
    for (int r = 0; r < 4; ++r) {
        stm[r] = -1e30f; stl[r] = 0.f;
        so[r][0] = so[r][1] = so[r][2] = 0.f;
    }

    float acc[2][2][4];
#pragma unroll
    for (int mt = 0; mt < 2; ++mt)
#pragma unroll
        for (int nt = 0; nt < 2; ++nt)
#pragma unroll
            for (int j = 0; j < 4; ++j) acc[mt][nt][j] = 0.f;

    cp16(S + SM_K + fko,                src_h);
    cp16(S + SM_K + fko + 16,           src_h + 16);
    cp16(S + SM_K + KLO_OFF + fko,      src_l);
    cp16(S + SM_K + KLO_OFF + fko + 16, src_l + 16);
    CP_COMMIT();

    for (int cc = 0; cc < 128; ++cc) {
        if (cc < 127) {
            const int nc = cc + 1;
            const u32 dst = S + SM_K + (u32)(nc & 1) * STAGE + fko;
            const size_t go = (size_t)(nc >> 4) * 131072 + (size_t)(nc & 15) * 64;
            cp16(dst,                src_h + go);
            cp16(dst + 16,           src_h + go + 16);
            cp16(dst + KLO_OFF,      src_l + go);
            cp16(dst + KLO_OFF + 16, src_l + go + 16);
            CP_COMMIT();
            CP_WAIT1();
        } else {
            CP_WAIT0();
        }
        __syncwarp();

        const u32 KB = S + SM_K + (u32)(cc & 1) * STAGE;
        const u32 chB = (u32)((cc & 15) * 64);
#pragma unroll
        for (int s = 0; s < 2; ++s) {
            const u32 qeB = chB + (u32)(s * 32);
            const u32 keB = (u32)(s * 32);
            u32 ah[2][4], al[2][4], bh[4], bl[4];
#pragma unroll
            for (int mt = 0; mt < 2; ++mt) {
                ldsm4(ah[mt], S + SM_QH + qoff[mt] + qeB);
                ldsm4(al[mt], S + SM_QL + qoff[mt] + qeB);
            }
            ldsm4(bh, KB + koff + keB);
            ldsm4(bl, KB + KLO_OFF + koff + keB);
#pragma unroll
            for (int mt = 0; mt < 2; ++mt) {
                mma16816(acc[mt][0], ah[mt], &bh[0]);
                mma16816(acc[mt][0], ah[mt], &bl[0]);
                mma16816(acc[mt][0], al[mt], &bh[0]);
                mma16816(acc[mt][1], ah[mt], &bh[2]);
                mma16816(acc[mt][1], ah[mt], &bl[2]);
                mma16816(acc[mt][1], al[mt], &bh[2]);
            }
        }

        if ((cc & 15) == 15) {
            const int m0 = (cc >> 4) * 128;
            const int c0 = kg * 16 + (lane & 3) * 2;
            const float kk0 = __ldg(kkb + m0 + c0);
            const float kk1 = __ldg(kkb + m0 + c0 + 1);
            const float kk2 = __ldg(kkb + m0 + c0 + 8);
            const float kk3 = __ldg(kkb + m0 + c0 + 9);
#pragma unroll
            for (int mt = 0; mt < 2; ++mt)
#pragma unroll
                for (int h = 0; h < 2; ++h) {
                    const int r = mt * 2 + h;
                    float lg[4];
                    lg[0] = fmaf(2.f, acc[mt][0][h*2+0], -kk0);
                    lg[1] = fmaf(2.f, acc[mt][0][h*2+1], -kk1);
                    lg[2] = fmaf(2.f, acc[mt][1][h*2+0], -kk2);
                    lg[3] = fmaf(2.f, acc[mt][1][h*2+1], -kk3);
                    const float vmax = fmaxf(fmaxf(lg[0], lg[1]), fmaxf(lg[2], lg[3]));
                    if (vmax >= stm[r] - 30.f) {
                        const float nm = fmaxf(stm[r], vmax);
                        const float sc = __expf(stm[r] - nm);
                        stl[r] *= sc; so[r][0] *= sc; so[r][1] *= sc; so[r][2] *= sc;
                        const float p0 = __expf(lg[0] - nm);
                        const float p1 = __expf(lg[1] - nm);
                        const float p2 = __expf(lg[2] - nm);
                        const float p3 = __expf(lg[3] - nm);
                        stl[r] += (p0 + p1) + (p2 + p3);
#pragma unroll
                        for (int d = 0; d < 3; ++d) {
                            const float* tp = tgtb + d * MM + m0 + c0;
                            so[r][d] += p0 * __ldg(tp) + p1 * __ldg(tp + 1)
                                      + p2 * __ldg(tp + 8) + p3 * __ldg(tp + 9);
                        }
                        stm[r] = nm;
                    }
                    acc[mt][0][h*2+0] = 0.f; acc[mt][0][h*2+1] = 0.f;
                    acc[mt][1][h*2+0] = 0.f; acc[mt][1][h*2+1] = 0.f;
                }
        }
    }

#pragma unroll
    for (int mt = 0; mt < 2; ++mt)
#pragma unroll
        for (int h = 0; h < 2; ++h) {
            const int r = mt * 2 + h;
            float m = stm[r], l = stl[r];
            float o0 = so[r][0], o1 = so[r][1], o2 = so[r][2];
#pragma unroll
            for (int off = 1; off < 4; off <<= 1) {
                float om = __shfl_xor_sync(0xffffffffu, m,  off, 4);
                float ol = __shfl_xor_sync(0xffffffffu, l,  off, 4);
                float p0 = __shfl_xor_sync(0xffffffffu, o0, off, 4);
                float p1 = __shfl_xor_sync(0xffffffffu, o1, off, 4);
                float p2 = __shfl_xor_sync(0xffffffffu, o2, off, 4);
                const float nm = fmaxf(m, om);
                const float sa = __expf(m - nm), sb = __expf(om - nm);
                l = l * sa + ol * sb;
                o0 = o0 * sa + p0 * sb; o1 = o1 * sa + p1 * sb; o2 = o2 * sa + p2 * sb;
                m = nm;
            }
            if ((lane & 3) == 0) {
                const int n = n0 + mt * 16 + h * 8 + (lane >> 2);
                const size_t pidx = (size_t)(blockIdx.y * 8 + kg) * (BB * NN)
                                  + (size_t)b * NN + n;
                g_pm[pidx] = m; g_pl[pidx] = l;
                g_po[3 * pidx + 0] = o0; g_po[3 * pidx + 1] = o1; g_po[3 * pidx + 2] = o2;
            }
        }
}

// ---------------------------------------------------------------------------
__global__ void merge_kernel(float* __restrict__ out_corr)
{
    const int idx = blockIdx.x * 256 + threadIdx.x;
    if (idx >= BB * NN) return;
    const int b = idx >> 12, n = idx & (NN - 1);
    float m = -1e30f;
#pragma unroll
    for (int s = 0; s < 32; ++s) m = fmaxf(m, g_pm[s * BB * NN + idx]);
    float l = 0.f, o0 = 0.f, o1 = 0.f, o2 = 0.f;
#pragma unroll
    for (int s = 0; s < 32; ++s) {
        const size_t p = (size_t)s * BB * NN + idx;
        const float w = __expf(g_pm[p] - m);
        l += g_pl[p] * w;
        o0 += g_po[3 * p + 0] * w; o1 += g_po[3 * p + 1] * w; o2 += g_po[3 * p + 2] * w;
    }
    const float inv = 1.f / l;
    out_corr[((size_t)b * 3 + 0) * NN + n] = o0 * inv;
    out_corr[((size_t)b * 3 + 1) * NN + n] = o1 * inv;
    out_corr[((size_t)b * 3 + 2) * NN + n] = o2 * inv;
}

__global__ void copy_src_kernel(const float* __restrict__ src, float* __restrict__ out)
{
    const int i = blockIdx.x * 256 + threadIdx.x;
    if (i < BB * 3 * NN) out[i] = src[i];
}

// ---------------------------------------------------------------------------
extern "C" void kernel_launch(void* const* d_in, const int* in_sizes, int n_in,
                              void* d_out, int out_size)
{
    const float* src_emb = (const float*)d_in[0];
    const float* tgt_emb = (const float*)d_in[1];
    const float* src     = (const float*)d_in[2];
    const float* tgt     = (const float*)d_in[3];
    const float* Wq      = (const float*)d_in[4];
    const float* bq      = (const float*)d_in[5];
    const float* Wk      = (const float*)d_in[6];
    const float* bk      = (const float*)d_in[7];
    float* out = (float*)d_out;

    const int corr_elems = BB * 3 * NN;
    const bool tuple_out = (out_size >= 2 * corr_elems);
    float* corr_out = tuple_out ? (out + corr_elems) : out;

    splitW_kernel<<<EE * EE / 1024, 256>>>(Wq, 0);
    splitW_kernel<<<EE * EE / 1024, 256>>>(Wk, 1);
    splitX_kernel<<<dim3(NN / 64, EE / 64, BB), 256>>>(src_emb, 0);
    splitX_kernel<<<dim3(MM / 64, EE / 64, BB), 256>>>(tgt_emb, 1);

    cudaFuncSetAttribute(projmma_kernel, cudaFuncAttributeMaxDynamicSharedMemorySize,
                         SMEM_TOTAL);
    projmma_kernel<<<dim3(256, 4), 256, SMEM_TOTAL>>>(bq, 0);
    projmma_kernel<<<dim3(256, 4), 256, SMEM_TOTAL>>>(bk, 1);

    kk_kernel<<<BB * MM / 8, 256>>>();

    cudaFuncSetAttribute(attn_kernel, cudaFuncAttributeMaxDynamicSharedMemorySize,
                         SMEM_TOTAL);
    attn_kernel<<<dim3(256, 4), 256, SMEM_TOTAL>>>(tgt);

    merge_kernel<<<(BB * NN + 255) / 256, 256>>>(corr_out);
    if (tuple_out)
        copy_src_kernel<<<(corr_elems + 255) / 256, 256>>>(src, out);
}

// round 11
// speedup vs baseline: 1.7610x; 1.2001x over previous
#include <cuda_runtime.h>
#include <cuda_bf16.h>
#include <cuda_fp16.h>
#include <stdint.h>

#define BB 2
#define EE 512
#define NN 4096
#define MM 4096

typedef unsigned long long u64;
typedef unsigned int u32;

// ---- scratch ---------------------------------------------------------------
__device__ __nv_bfloat16 g_Qhi[BB * NN * EE], g_Qlo[BB * NN * EE];
__device__ __nv_bfloat16 g_Khi[BB * MM * EE], g_Klo[BB * MM * EE];
__device__ __nv_bfloat16 g_XQhi[BB * NN * EE], g_XQlo[BB * NN * EE];
__device__ __nv_bfloat16 g_XKhi[BB * MM * EE], g_XKlo[BB * MM * EE];
__device__ __nv_bfloat16 g_Whi[2 * EE * EE], g_Wlo[2 * EE * EE];
__device__ float g_kk[BB * MM];
__device__ __half g_est[(size_t)BB * NN * MM];   // approximate logits (64 MB)

// ---- PTX helpers (portable, no 'a'-features) -------------------------------
__device__ __forceinline__ u32 smem_u32(const void* p) {
    u32 a;
    asm("{ .reg .u64 t; cvta.to.shared.u64 t, %1; cvt.u32.u64 %0, t; }" : "=r"(a) : "l"(p));
    return a;
}
__device__ __forceinline__ void cp16(u32 dst, const void* src) {
    asm volatile("cp.async.cg.shared.global [%0], [%1], 16;" :: "r"(dst), "l"(src) : "memory");
}
#define CP_COMMIT() asm volatile("cp.async.commit_group;" ::: "memory")
#define CP_WAIT0()  asm volatile("cp.async.wait_group 0;" ::: "memory")
#define CP_WAIT1()  asm volatile("cp.async.wait_group 1;" ::: "memory")

__device__ __forceinline__ void ldsm4(u32* r, u32 a) {
    asm volatile("ldmatrix.sync.aligned.m8n8.x4.shared.b16 {%0,%1,%2,%3}, [%4];"
                 : "=r"(r[0]), "=r"(r[1]), "=r"(r[2]), "=r"(r[3]) : "r"(a));
}
__device__ __forceinline__ void mma16816(float* c, const u32* a, const u32* b) {
    asm volatile(
        "mma.sync.aligned.m16n8k16.row.col.f32.bf16.bf16.f32 "
        "{%0,%1,%2,%3}, {%4,%5,%6,%7}, {%8,%9}, {%0,%1,%2,%3};"
        : "+f"(c[0]), "+f"(c[1]), "+f"(c[2]), "+f"(c[3])
        : "r"(a[0]), "r"(a[1]), "r"(a[2]), "r"(a[3]), "r"(b[0]), "r"(b[1]));
}
__device__ __forceinline__ u32 packbf(__nv_bfloat16 a, __nv_bfloat16 b) {
    __nv_bfloat162 t; t.x = a; t.y = b;
    return *reinterpret_cast<u32*>(&t);
}

// ---------------------------------------------------------------------------
// split W: [f][e] fp32 -> bf16 hi/lo
// ---------------------------------------------------------------------------
__global__ __launch_bounds__(256) void splitW_kernel(const float* __restrict__ W, int slot)
{
    const int i = (blockIdx.x * 256 + threadIdx.x) * 4;
    float4 v = *(const float4*)(W + i);
    float x[4] = {v.x, v.y, v.z, v.w};
    __nv_bfloat16 h[4]; float l[4];
#pragma unroll
    for (int k = 0; k < 4; ++k) {
        h[k] = __float2bfloat16_rn(x[k]);
        l[k] = x[k] - __bfloat162float(h[k]);
    }
    uint2 ph, pl;
    ph.x = packbf(h[0], h[1]); ph.y = packbf(h[2], h[3]);
    pl.x = packbf(__float2bfloat16_rn(l[0]), __float2bfloat16_rn(l[1]));
    pl.y = packbf(__float2bfloat16_rn(l[2]), __float2bfloat16_rn(l[3]));
    const size_t off = (size_t)slot * EE * EE + i;
    *(uint2*)(g_Whi + off) = ph;
    *(uint2*)(g_Wlo + off) = pl;
}

// ---------------------------------------------------------------------------
// split+transpose X: [b][e][n] fp32 -> bf16 hi/lo [b][n][e]
// ---------------------------------------------------------------------------
__global__ __launch_bounds__(256) void splitX_kernel(const float* __restrict__ X, int which)
{
    __nv_bfloat16* __restrict__ Yh = which ? g_XKhi : g_XQhi;
    __nv_bfloat16* __restrict__ Yl = which ? g_XKlo : g_XQlo;
    __shared__ float tile[64][65];
    const int tid = threadIdx.x;
    const int n0 = blockIdx.x * 64, e0 = blockIdx.y * 64, b = blockIdx.z;
    const float* Xb = X + (size_t)b * EE * NN;

    const int lr = tid >> 4, n4 = tid & 15;
#pragma unroll
    for (int it = 0; it < 4; ++it) {
        const int e = lr + it * 16;
        float4 v = *(const float4*)(Xb + (size_t)(e0 + e) * NN + n0 + n4 * 4);
        tile[e][n4*4+0] = v.x; tile[e][n4*4+1] = v.y;
        tile[e][n4*4+2] = v.z; tile[e][n4*4+3] = v.w;
    }
    __syncthreads();

    const int n = tid >> 2, et = tid & 3;
    u32 hw[8], lw[8];
#pragma unroll
    for (int k = 0; k < 8; ++k) {
        const float a = tile[et*16 + 2*k][n], c = tile[et*16 + 2*k + 1][n];
        __nv_bfloat16 ha = __float2bfloat16_rn(a), hc = __float2bfloat16_rn(c);
        hw[k] = packbf(ha, hc);
        lw[k] = packbf(__float2bfloat16_rn(a - __bfloat162float(ha)),
                       __float2bfloat16_rn(c - __bfloat162float(hc)));
    }
    const size_t base = ((size_t)b * NN + n0 + n) * EE + e0 + et * 16;
    *(uint4*)(Yh + base)     = *(uint4*)(hw);
    *(uint4*)(Yh + base + 8) = *(uint4*)(hw + 4);
    *(uint4*)(Yl + base)     = *(uint4*)(lw);
    *(uint4*)(Yl + base + 8) = *(uint4*)(lw + 4);
}

// ---------------------------------------------------------------------------
// proj via mma (3-term split), warp-autonomous. Unchanged from round 10.
// ---------------------------------------------------------------------------
#define QPITCH 1040
#define SM_QH 0
#define SM_QL 33280
#define SM_K  66560
#define KPITCH 80
#define KLO_OFF 10240
#define STAGE 20480
#define SMEM_TOTAL 107520

__global__ __launch_bounds__(256, 2) void projmma_kernel(const float* __restrict__ bias,
                                                         int which)
{
    extern __shared__ char smraw[];
    const u32 S = smem_u32(smraw);
    const int tid = threadIdx.x, kg = tid >> 5, lane = tid & 31;
    const int b = blockIdx.x >> 7, n0 = (blockIdx.x & 127) * 32;
    const int f0 = blockIdx.y * 128;
    const __nv_bfloat16* Axh = which ? g_XKhi : g_XQhi;
    const __nv_bfloat16* Axl = which ? g_XKlo : g_XQlo;
    __nv_bfloat16* Oh = which ? g_Khi : g_Qhi;
    __nv_bfloat16* Ol = which ? g_Klo : g_Qlo;
    const char* Wh = (const char*)(g_Whi + (size_t)which * EE * EE);
    const char* Wl = (const char*)(g_Wlo + (size_t)which * EE * EE);

    {
        const char* ah = (const char*)(Axh + (size_t)(b * NN + n0) * EE);
        const char* al = (const char*)(Axl + (size_t)(b * NN + n0) * EE);
#pragma unroll
        for (int it = 0; it < 8; ++it) {
            const int i = tid + it * 256;
            const int row = i >> 6, g = (i & 63) * 16;
            cp16(S + SM_QH + row * QPITCH + g, ah + row * 1024 + g);
            cp16(S + SM_QL + row * QPITCH + g, al + row * 1024 + g);
        }
        CP_COMMIT(); CP_WAIT0();
        __syncthreads();
    }

    const int laneQrow = (lane & 7) + ((lane >> 3) & 1) * 8;
    const int laneQcolB = (lane >> 4) * 16;
    const int laneKn = (lane & 7) + ((lane >> 4) & 1) * 8;
    const int laneKeB = ((lane >> 3) & 1) * 16;
    u32 qoff[2];
    qoff[0] = (u32)(laneQrow * QPITCH + laneQcolB);
    qoff[1] = qoff[0] + 16 * QPITCH;
    const u32 koff = (u32)((kg * 16 + laneKn) * KPITCH + laneKeB);

    const u32 fko = (u32)((kg * 16 + (lane >> 1)) * KPITCH + (lane & 1) * 32);
    const char* sWh = Wh + (size_t)(f0 + kg * 16 + (lane >> 1)) * 1024 + (lane & 1) * 32;
    const char* sWl = Wl + (size_t)(f0 + kg * 16 + (lane >> 1)) * 1024 + (lane & 1) * 32;

    float acc[2][2][4];
#pragma unroll
    for (int mt = 0; mt < 2; ++mt)
#pragma unroll
        for (int nt = 0; nt < 2; ++nt)
#pragma unroll
            for (int j = 0; j < 4; ++j) acc[mt][nt][j] = 0.f;

    cp16(S + SM_K + fko,                sWh);
    cp16(S + SM_K + fko + 16,           sWh + 16);
    cp16(S + SM_K + KLO_OFF + fko,      sWl);
    cp16(S + SM_K + KLO_OFF + fko + 16, sWl + 16);
    CP_COMMIT();

    for (int cc = 0; cc < 16; ++cc) {
        if (cc < 15) {
            const int nc = cc + 1;
            const u32 dst = S + SM_K + (u32)(nc & 1) * STAGE + fko;
            const size_t go = (size_t)nc * 64;
            cp16(dst,                sWh + go);
            cp16(dst + 16,           sWh + go + 16);
            cp16(dst + KLO_OFF,      sWl + go);
            cp16(dst + KLO_OFF + 16, sWl + go + 16);
            CP_COMMIT();
            CP_WAIT1();
        } else {
            CP_WAIT0();
        }
        __syncwarp();
        const u32 KB = S + SM_K + (u32)(cc & 1) * STAGE;
        const u32 chB = (u32)(cc * 64);
#pragma unroll
        for (int s = 0; s < 2; ++s) {
            const u32 qeB = chB + (u32)(s * 32);
            const u32 keB = (u32)(s * 32);
            u32 ah[2][4], al[2][4], bh[4], bl[4];
#pragma unroll
            for (int mt = 0; mt < 2; ++mt) {
                ldsm4(ah[mt], S + SM_QH + qoff[mt] + qeB);
                ldsm4(al[mt], S + SM_QL + qoff[mt] + qeB);
            }
            ldsm4(bh, KB + koff + keB);
            ldsm4(bl, KB + KLO_OFF + koff + keB);
#pragma unroll
            for (int mt = 0; mt < 2; ++mt) {
                mma16816(acc[mt][0], ah[mt], &bh[0]);
                mma16816(acc[mt][0], ah[mt], &bl[0]);
                mma16816(acc[mt][0], al[mt], &bh[0]);
                mma16816(acc[mt][1], ah[mt], &bh[2]);
                mma16816(acc[mt][1], ah[mt], &bl[2]);
                mma16816(acc[mt][1], al[mt], &bh[2]);
            }
        }
    }

    __syncthreads();
    float bias2[2][2];
#pragma unroll
    for (int nt = 0; nt < 2; ++nt)
#pragma unroll
        for (int j = 0; j < 2; ++j)
            bias2[nt][j] = __ldg(bias + f0 + kg * 16 + nt * 8 + (lane & 3) * 2 + j);
    __nv_bfloat16* sh = (__nv_bfloat16*)(smraw + SM_K);
    __nv_bfloat16* sl = (__nv_bfloat16*)(smraw + SM_K + 8192);
#pragma unroll
    for (int mt = 0; mt < 2; ++mt)
#pragma unroll
        for (int nt = 0; nt < 2; ++nt)
#pragma unroll
            for (int c = 0; c < 4; ++c) {
                const int row = mt * 16 + (lane >> 2) + (c >> 1) * 8;
                const int col = kg * 16 + nt * 8 + (lane & 3) * 2 + (c & 1);
                const float q = acc[mt][nt][c] + bias2[nt][c & 1];
                const __nv_bfloat16 h = __float2bfloat16_rn(q);
                sh[row * 128 + col] = h;
                sl[row * 128 + col] = __float2bfloat16_rn(q - __bfloat162float(h));
            }
    __syncthreads();
    {
        const int row = tid >> 3, seg = tid & 7;
        const size_t gbase = ((size_t)(b * NN + n0 + row)) * EE + f0 + seg * 16;
        const int sbase = row * 128 + seg * 16;
        *(uint4*)(Oh + gbase)     = *(uint4*)(sh + sbase);
        *(uint4*)(Oh + gbase + 8) = *(uint4*)(sh + sbase + 8);
        *(uint4*)(Ol + gbase)     = *(uint4*)(sl + sbase);
        *(uint4*)(Ol + gbase + 8) = *(uint4*)(sl + sbase + 8);
    }
}

// ---------------------------------------------------------------------------
__global__ __launch_bounds__(256) void kk_kernel()
{
    const int row = blockIdx.x * 8 + (threadIdx.x >> 5);
    const int lane = threadIdx.x & 31;
    const uint4* h4 = (const uint4*)(g_Khi + (size_t)row * EE);
    const uint4* l4 = (const uint4*)(g_Klo + (size_t)row * EE);
    float s = 0.f;
#pragma unroll
    for (int it = 0; it < 2; ++it) {
        uint4 h = h4[lane + it * 32], l = l4[lane + it * 32];
        const __nv_bfloat162* hp = (const __nv_bfloat162*)&h;
        const __nv_bfloat162* lp = (const __nv_bfloat162*)&l;
#pragma unroll
        for (int k = 0; k < 4; ++k) {
            float2 fh = __bfloat1622float2(hp[k]);
            float2 fl = __bfloat1622float2(lp[k]);
            float x = fh.x + fl.x, y = fh.y + fl.y;
            s = fmaf(x, x, fmaf(y, y, s));
        }
    }
#pragma unroll
    for (int off = 16; off; off >>= 1) s += __shfl_xor_sync(0xffffffffu, s, off);
    if (lane == 0) g_kk[row] = s;
}

// ---------------------------------------------------------------------------
// Phase 1: hi*hi approximate logits -> g_est (fp16). Warp-autonomous, 3 CTAs/SM.
// grid (256, 8): b = bx>>7, n-tile = bx&127 (32 rows), by = 512-key split.
// ---------------------------------------------------------------------------
#define P1_SMK 33280
#define P1_STAGE 10240
#define P1_TOTAL 53760

__global__ __launch_bounds__(256, 3) void est_kernel()
{
    extern __shared__ char smraw[];
    const u32 S = smem_u32(smraw);
    const int tid = threadIdx.x, kg = tid >> 5, lane = tid & 31;
    const int b = blockIdx.x >> 7, n0 = (blockIdx.x & 127) * 32;
    const int mbase = blockIdx.y * 512;

    {   // Qhi tile fill
        const char* qh = (const char*)(g_Qhi + (size_t)(b * NN + n0) * EE);
#pragma unroll
        for (int it = 0; it < 8; ++it) {
            const int i = tid + it * 256;
            const int row = i >> 6, g = (i & 63) * 16;
            cp16(S + row * QPITCH + g, qh + row * 1024 + g);
        }
        CP_COMMIT(); CP_WAIT0();
        __syncthreads();
    }

    const int laneQrow = (lane & 7) + ((lane >> 3) & 1) * 8;
    const int laneQcolB = (lane >> 4) * 16;
    const int laneKn = (lane & 7) + ((lane >> 4) & 1) * 8;
    const int laneKeB = ((lane >> 3) & 1) * 16;
    u32 qoff[2];
    qoff[0] = (u32)(laneQrow * QPITCH + laneQcolB);
    qoff[1] = qoff[0] + 16 * QPITCH;
    const u32 koff = (u32)((kg * 16 + laneKn) * KPITCH + laneKeB);
    const u32 fko = (u32)((kg * 16 + (lane >> 1)) * KPITCH + (lane & 1) * 32);
    const char* src_h = (const char*)g_Khi
        + ((size_t)(b * MM + mbase + kg * 16 + (lane >> 1))) * 1024 + (lane & 1) * 32;

    const float* kkb = g_kk + b * MM + mbase;
    __half* estb = g_est + ((size_t)(b * NN + n0)) * MM + mbase;

    float acc[2][2][4];
#pragma unroll
    for (int mt = 0; mt < 2; ++mt)
#pragma unroll
        for (int nt = 0; nt < 2; ++nt)
#pragma unroll
            for (int j = 0; j < 4; ++j) acc[mt][nt][j] = 0.f;

    cp16(S + P1_SMK + fko,      src_h);
    cp16(S + P1_SMK + fko + 16, src_h + 16);
    CP_COMMIT();

    for (int cc = 0; cc < 64; ++cc) {
        if (cc < 63) {
            const int nc = cc + 1;
            const u32 dst = S + P1_SMK + (u32)(nc & 1) * P1_STAGE + fko;
            const size_t go = (size_t)(nc >> 4) * 131072 + (size_t)(nc & 15) * 64;
            cp16(dst,      src_h + go);
            cp16(dst + 16, src_h + go + 16);
            CP_COMMIT();
            CP_WAIT1();
        } else {
            CP_WAIT0();
        }
        __syncwarp();

        const u32 KB = S + P1_SMK + (u32)(cc & 1) * P1_STAGE;
        const u32 chB = (u32)((cc & 15) * 64);
#pragma unroll
        for (int s = 0; s < 2; ++s) {
            const u32 qeB = chB + (u32)(s * 32);
            u32 ah[2][4], bh[4];
            ldsm4(ah[0], S + qoff[0] + qeB);
            ldsm4(ah[1], S + qoff[1] + qeB);
            ldsm4(bh, KB + koff + (u32)(s * 32));
#pragma unroll
            for (int mt = 0; mt < 2; ++mt) {
                mma16816(acc[mt][0], ah[mt], &bh[0]);
                mma16816(acc[mt][1], ah[mt], &bh[2]);
            }
        }

        if ((cc & 15) == 15) {
            const int m0 = (cc >> 4) * 128;
            const int c0 = kg * 16 + (lane & 3) * 2;
            const float kk0 = __ldg(kkb + m0 + c0);
            const float kk1 = __ldg(kkb + m0 + c0 + 1);
            const float kk2 = __ldg(kkb + m0 + c0 + 8);
            const float kk3 = __ldg(kkb + m0 + c0 + 9);
#pragma unroll
            for (int mt = 0; mt < 2; ++mt)
#pragma unroll
                for (int h = 0; h < 2; ++h) {
                    const int row = mt * 16 + h * 8 + (lane >> 2);
                    __half* ep = estb + (size_t)row * MM + m0 + c0;
                    float2 fa = make_float2(fmaf(2.f, acc[mt][0][h*2+0], -kk0),
                                            fmaf(2.f, acc[mt][0][h*2+1], -kk1));
                    float2 fb = make_float2(fmaf(2.f, acc[mt][1][h*2+0], -kk2),
                                            fmaf(2.f, acc[mt][1][h*2+1], -kk3));
                    *reinterpret_cast<__half2*>(ep)     = __float22half2_rn(fa);
                    *reinterpret_cast<__half2*>(ep + 8) = __float22half2_rn(fb);
                    acc[mt][0][h*2+0] = 0.f; acc[mt][0][h*2+1] = 0.f;
                    acc[mt][1][h*2+0] = 0.f; acc[mt][1][h*2+1] = 0.f;
                }
        }
    }
}

// ---------------------------------------------------------------------------
// Phase 2: per-row scan of est logits, exact fp32 recompute of live keys,
// exact softmax + weighted tgt sum -> out. One warp per q-row.
// ---------------------------------------------------------------------------
__global__ __launch_bounds__(256) void gather_kernel(const float* __restrict__ tgt,
                                                     float* __restrict__ out_corr)
{
    const int w = blockIdx.x * 8 + (threadIdx.x >> 5);   // 0..8191 = b*NN + n
    const int lane = threadIdx.x & 31;
    const int b = w >> 12, n = w & (NN - 1);

    // q row slice (16 e per lane), exact reconstruct
    float qf[16];
    {
        const uint4* qh = (const uint4*)(g_Qhi + (size_t)w * EE + lane * 16);
        const uint4* ql = (const uint4*)(g_Qlo + (size_t)w * EE + lane * 16);
        uint4 H[2] = {qh[0], qh[1]}, L[2] = {ql[0], ql[1]};
#pragma unroll
        for (int g = 0; g < 2; ++g) {
            const __nv_bfloat162* hp = (const __nv_bfloat162*)&H[g];
            const __nv_bfloat162* lp = (const __nv_bfloat162*)&L[g];
#pragma unroll
            for (int j = 0; j < 4; ++j) {
                float2 fh = __bfloat1622float2(hp[j]);
                float2 fl = __bfloat1622float2(lp[j]);
                qf[g*8 + j*2 + 0] = fh.x + fl.x;
                qf[g*8 + j*2 + 1] = fh.y + fl.y;
            }
        }
    }

    const __half* er = g_est + (size_t)w * MM;
    float rmax = -1e30f;
#pragma unroll
    for (int it = 0; it < 16; ++it) {
        uint4 v = *(const uint4*)(er + it * 256 + lane * 8);
        const __half2* hp = (const __half2*)&v;
#pragma unroll
        for (int j = 0; j < 4; ++j) {
            float2 f = __half22float2(hp[j]);
            rmax = fmaxf(rmax, fmaxf(f.x, f.y));
        }
    }
#pragma unroll
    for (int off = 16; off; off >>= 1)
        rmax = fmaxf(rmax, __shfl_xor_sync(0xffffffffu, rmax, off));
    const float T = rmax - 25.f;

    const float* kkb = g_kk + b * MM;
    const float* tb  = tgt + (size_t)b * 3 * MM;
    float m = -1e30f, sl = 0.f, o0 = 0.f, o1 = 0.f, o2 = 0.f;

    for (int blk = 0; blk < 128; ++blk) {
        const float e = __half2float(er[blk * 32 + lane]);
        u32 mask = __ballot_sync(0xffffffffu, e >= T);
        while (mask) {
            const int kix = blk * 32 + (__ffs(mask) - 1);
            mask &= mask - 1;
            const uint4* kh = (const uint4*)(g_Khi + (size_t)(b * MM + kix) * EE + lane * 16);
            const uint4* kl = (const uint4*)(g_Klo + (size_t)(b * MM + kix) * EE + lane * 16);
            uint4 H[2] = {kh[0], kh[1]}, L[2] = {kl[0], kl[1]};
            float d = 0.f;
#pragma unroll
            for (int g = 0; g < 2; ++g) {
                const __nv_bfloat162* hp = (const __nv_bfloat162*)&H[g];
                const __nv_bfloat162* lp = (const __nv_bfloat162*)&L[g];
#pragma unroll
                for (int j = 0; j < 4; ++j) {
                    float2 fh = __bfloat1622float2(hp[j]);
                    float2 fl = __bfloat1622float2(lp[j]);
                    d = fmaf(qf[g*8 + j*2 + 0], fh.x + fl.x, d);
                    d = fmaf(qf[g*8 + j*2 + 1], fh.y + fl.y, d);
                }
            }
#pragma unroll
            for (int off = 16; off; off >>= 1)
                d += __shfl_xor_sync(0xffffffffu, d, off);
            if (lane == 0) {
                const float lg = fmaf(2.f, d, -__ldg(kkb + kix));
                const float nm = fmaxf(m, lg);
                const float sc = __expf(m - nm);
                const float p  = __expf(lg - nm);
                sl = sl * sc + p;
                o0 = o0 * sc + p * __ldg(tb + kix);
                o1 = o1 * sc + p * __ldg(tb + MM + kix);
                o2 = o2 * sc + p * __ldg(tb + 2 * MM + kix);
                m = nm;
            }
        }
    }

    if (lane == 0) {
        const float inv = 1.f / sl;
        out_corr[(size_t)b * 3 * NN + n]          = o0 * inv;
        out_corr[(size_t)b * 3 * NN + NN + n]     = o1 * inv;
        out_corr[(size_t)b * 3 * NN + 2 * NN + n] = o2 * inv;
    }
}

__global__ void copy_src_kernel(const float* __restrict__ src, float* __restrict__ out)
{
    const int i = blockIdx.x * 256 + threadIdx.x;
    if (i < BB * 3 * NN) out[i] = src[i];
}

// ---------------------------------------------------------------------------
extern "C" void kernel_launch(void* const* d_in, const int* in_sizes, int n_in,
                              void* d_out, int out_size)
{
    const float* src_emb = (const float*)d_in[0];
    const float* tgt_emb = (const float*)d_in[1];
    const float* src     = (const float*)d_in[2];
    const float* tgt     = (const float*)d_in[3];
    const float* Wq      = (const float*)d_in[4];
    const float* bq      = (const float*)d_in[5];
    const float* Wk      = (const float*)d_in[6];
    const float* bk      = (const float*)d_in[7];
    float* out = (float*)d_out;

    const int corr_elems = BB * 3 * NN;
    const bool tuple_out = (out_size >= 2 * corr_elems);
    float* corr_out = tuple_out ? (out + corr_elems) : out;

    splitW_kernel<<<EE * EE / 1024, 256>>>(Wq, 0);
    splitW_kernel<<<EE * EE / 1024, 256>>>(Wk, 1);
    splitX_kernel<<<dim3(NN / 64, EE / 64, BB), 256>>>(src_emb, 0);
    splitX_kernel<<<dim3(MM / 64, EE / 64, BB), 256>>>(tgt_emb, 1);

    cudaFuncSetAttribute(projmma_kernel, cudaFuncAttributeMaxDynamicSharedMemorySize,
                         SMEM_TOTAL);
    projmma_kernel<<<dim3(256, 4), 256, SMEM_TOTAL>>>(bq, 0);
    projmma_kernel<<<dim3(256, 4), 256, SMEM_TOTAL>>>(bk, 1);

    kk_kernel<<<BB * MM / 8, 256>>>();

    cudaFuncSetAttribute(est_kernel, cudaFuncAttributeMaxDynamicSharedMemorySize,
                         P1_TOTAL);
    est_kernel<<<dim3(256, 8), 256, P1_TOTAL>>>();

    gather_kernel<<<BB * NN / 8, 256>>>(tgt, corr_out);

    if (tuple_out)
        copy_src_kernel<<<(corr_elems + 255) / 256, 256>>>(src, out);
}

// round 12
// speedup vs baseline: 1.8266x; 1.0373x over previous
#include <cuda_runtime.h>
#include <cuda_bf16.h>
#include <cuda_fp16.h>
#include <stdint.h>

#define BB 2
#define EE 512
#define NN 4096
#define MM 4096

typedef unsigned long long u64;
typedef unsigned int u32;

// ---- scratch ---------------------------------------------------------------
__device__ __nv_bfloat16 g_Qhi[BB * NN * EE], g_Qlo[BB * NN * EE];
__device__ __nv_bfloat16 g_Khi[BB * MM * EE], g_Klo[BB * MM * EE];
__device__ __nv_bfloat16 g_XQhi[BB * NN * EE], g_XQlo[BB * NN * EE];
__device__ __nv_bfloat16 g_XKhi[BB * MM * EE], g_XKlo[BB * MM * EE];
__device__ __nv_bfloat16 g_Whi[2 * EE * EE], g_Wlo[2 * EE * EE];
__device__ float g_kk[BB * MM];
__device__ __half g_est[(size_t)BB * NN * MM];   // approximate logits (64 MB)

// ---- PTX helpers (portable, no 'a'-features) -------------------------------
__device__ __forceinline__ u32 smem_u32(const void* p) {
    u32 a;
    asm("{ .reg .u64 t; cvta.to.shared.u64 t, %1; cvt.u32.u64 %0, t; }" : "=r"(a) : "l"(p));
    return a;
}
__device__ __forceinline__ void cp16(u32 dst, const void* src) {
    asm volatile("cp.async.cg.shared.global [%0], [%1], 16;" :: "r"(dst), "l"(src) : "memory");
}
#define CP_COMMIT() asm volatile("cp.async.commit_group;" ::: "memory")
#define CP_WAIT0()  asm volatile("cp.async.wait_group 0;" ::: "memory")
#define CP_WAIT1()  asm volatile("cp.async.wait_group 1;" ::: "memory")

__device__ __forceinline__ void ldsm4(u32* r, u32 a) {
    asm volatile("ldmatrix.sync.aligned.m8n8.x4.shared.b16 {%0,%1,%2,%3}, [%4];"
                 : "=r"(r[0]), "=r"(r[1]), "=r"(r[2]), "=r"(r[3]) : "r"(a));
}
__device__ __forceinline__ void mma16816(float* c, const u32* a, const u32* b) {
    asm volatile(
        "mma.sync.aligned.m16n8k16.row.col.f32.bf16.bf16.f32 "
        "{%0,%1,%2,%3}, {%4,%5,%6,%7}, {%8,%9}, {%0,%1,%2,%3};"
        : "+f"(c[0]), "+f"(c[1]), "+f"(c[2]), "+f"(c[3])
        : "r"(a[0]), "r"(a[1]), "r"(a[2]), "r"(a[3]), "r"(b[0]), "r"(b[1]));
}
__device__ __forceinline__ u32 packbf(__nv_bfloat16 a, __nv_bfloat16 b) {
    __nv_bfloat162 t; t.x = a; t.y = b;
    return *reinterpret_cast<u32*>(&t);
}

// ---------------------------------------------------------------------------
// split W: [f][e] fp32 -> bf16 hi/lo
// ---------------------------------------------------------------------------
__global__ __launch_bounds__(256) void splitW_kernel(const float* __restrict__ W, int slot)
{
    const int i = (blockIdx.x * 256 + threadIdx.x) * 4;
    float4 v = *(const float4*)(W + i);
    float x[4] = {v.x, v.y, v.z, v.w};
    __nv_bfloat16 h[4]; float l[4];
#pragma unroll
    for (int k = 0; k < 4; ++k) {
        h[k] = __float2bfloat16_rn(x[k]);
        l[k] = x[k] - __bfloat162float(h[k]);
    }
    uint2 ph, pl;
    ph.x = packbf(h[0], h[1]); ph.y = packbf(h[2], h[3]);
    pl.x = packbf(__float2bfloat16_rn(l[0]), __float2bfloat16_rn(l[1]));
    pl.y = packbf(__float2bfloat16_rn(l[2]), __float2bfloat16_rn(l[3]));
    const size_t off = (size_t)slot * EE * EE + i;
    *(uint2*)(g_Whi + off) = ph;
    *(uint2*)(g_Wlo + off) = pl;
}

// ---------------------------------------------------------------------------
// split+transpose X: [b][e][n] fp32 -> bf16 hi/lo [b][n][e]
// ---------------------------------------------------------------------------
__global__ __launch_bounds__(256) void splitX_kernel(const float* __restrict__ X, int which)
{
    __nv_bfloat16* __restrict__ Yh = which ? g_XKhi : g_XQhi;
    __nv_bfloat16* __restrict__ Yl = which ? g_XKlo : g_XQlo;
    __shared__ float tile[64][65];
    const int tid = threadIdx.x;
    const int n0 = blockIdx.x * 64, e0 = blockIdx.y * 64, b = blockIdx.z;
    const float* Xb = X + (size_t)b * EE * NN;

    const int lr = tid >> 4, n4 = tid & 15;
#pragma unroll
    for (int it = 0; it < 4; ++it) {
        const int e = lr + it * 16;
        float4 v = *(const float4*)(Xb + (size_t)(e0 + e) * NN + n0 + n4 * 4);
        tile[e][n4*4+0] = v.x; tile[e][n4*4+1] = v.y;
        tile[e][n4*4+2] = v.z; tile[e][n4*4+3] = v.w;
    }
    __syncthreads();

    const int n = tid >> 2, et = tid & 3;
    u32 hw[8], lw[8];
#pragma unroll
    for (int k = 0; k < 8; ++k) {
        const float a = tile[et*16 + 2*k][n], c = tile[et*16 + 2*k + 1][n];
        __nv_bfloat16 ha = __float2bfloat16_rn(a), hc = __float2bfloat16_rn(c);
        hw[k] = packbf(ha, hc);
        lw[k] = packbf(__float2bfloat16_rn(a - __bfloat162float(ha)),
                       __float2bfloat16_rn(c - __bfloat162float(hc)));
    }
    const size_t base = ((size_t)b * NN + n0 + n) * EE + e0 + et * 16;
    *(uint4*)(Yh + base)     = *(uint4*)(hw);
    *(uint4*)(Yh + base + 8) = *(uint4*)(hw + 4);
    *(uint4*)(Yl + base)     = *(uint4*)(lw);
    *(uint4*)(Yl + base + 8) = *(uint4*)(lw + 4);
}

// ---------------------------------------------------------------------------
// proj via mma (3-term split), warp-autonomous. Unchanged.
// ---------------------------------------------------------------------------
#define QPITCH 1040
#define SM_QH 0
#define SM_QL 33280
#define SM_K  66560
#define KPITCH 80
#define KLO_OFF 10240
#define STAGE 20480
#define SMEM_TOTAL 107520

__global__ __launch_bounds__(256, 2) void projmma_kernel(const float* __restrict__ bias,
                                                         int which)
{
    extern __shared__ char smraw[];
    const u32 S = smem_u32(smraw);
    const int tid = threadIdx.x, kg = tid >> 5, lane = tid & 31;
    const int b = blockIdx.x >> 7, n0 = (blockIdx.x & 127) * 32;
    const int f0 = blockIdx.y * 128;
    const __nv_bfloat16* Axh = which ? g_XKhi : g_XQhi;
    const __nv_bfloat16* Axl = which ? g_XKlo : g_XQlo;
    __nv_bfloat16* Oh = which ? g_Khi : g_Qhi;
    __nv_bfloat16* Ol = which ? g_Klo : g_Qlo;
    const char* Wh = (const char*)(g_Whi + (size_t)which * EE * EE);
    const char* Wl = (const char*)(g_Wlo + (size_t)which * EE * EE);

    {
        const char* ah = (const char*)(Axh + (size_t)(b * NN + n0) * EE);
        const char* al = (const char*)(Axl + (size_t)(b * NN + n0) * EE);
#pragma unroll
        for (int it = 0; it < 8; ++it) {
            const int i = tid + it * 256;
            const int row = i >> 6, g = (i & 63) * 16;
            cp16(S + SM_QH + row * QPITCH + g, ah + row * 1024 + g);
            cp16(S + SM_QL + row * QPITCH + g, al + row * 1024 + g);
        }
        CP_COMMIT(); CP_WAIT0();
        __syncthreads();
    }

    const int laneQrow = (lane & 7) + ((lane >> 3) & 1) * 8;
    const int laneQcolB = (lane >> 4) * 16;
    const int laneKn = (lane & 7) + ((lane >> 4) & 1) * 8;
    const int laneKeB = ((lane >> 3) & 1) * 16;
    u32 qoff[2];
    qoff[0] = (u32)(laneQrow * QPITCH + laneQcolB);
    qoff[1] = qoff[0] + 16 * QPITCH;
    const u32 koff = (u32)((kg * 16 + laneKn) * KPITCH + laneKeB);

    const u32 fko = (u32)((kg * 16 + (lane >> 1)) * KPITCH + (lane & 1) * 32);
    const char* sWh = Wh + (size_t)(f0 + kg * 16 + (lane >> 1)) * 1024 + (lane & 1) * 32;
    const char* sWl = Wl + (size_t)(f0 + kg * 16 + (lane >> 1)) * 1024 + (lane & 1) * 32;

    float acc[2][2][4];
#pragma unroll
    for (int mt = 0; mt < 2; ++mt)
#pragma unroll
        for (int nt = 0; nt < 2; ++nt)
#pragma unroll
            for (int j = 0; j < 4; ++j) acc[mt][nt][j] = 0.f;

    cp16(S + SM_K + fko,                sWh);
    cp16(S + SM_K + fko + 16,           sWh + 16);
    cp16(S + SM_K + KLO_OFF + fko,      sWl);
    cp16(S + SM_K + KLO_OFF + fko + 16, sWl + 16);
    CP_COMMIT();

    for (int cc = 0; cc < 16; ++cc) {
        if (cc < 15) {
            const int nc = cc + 1;
            const u32 dst = S + SM_K + (u32)(nc & 1) * STAGE + fko;
            const size_t go = (size_t)nc * 64;
            cp16(dst,                sWh + go);
            cp16(dst + 16,           sWh + go + 16);
            cp16(dst + KLO_OFF,      sWl + go);
            cp16(dst + KLO_OFF + 16, sWl + go + 16);
            CP_COMMIT();
            CP_WAIT1();
        } else {
            CP_WAIT0();
        }
        __syncwarp();
        const u32 KB = S + SM_K + (u32)(cc & 1) * STAGE;
        const u32 chB = (u32)(cc * 64);
#pragma unroll
        for (int s = 0; s < 2; ++s) {
            const u32 qeB = chB + (u32)(s * 32);
            const u32 keB = (u32)(s * 32);
            u32 ah[2][4], al[2][4], bh[4], bl[4];
#pragma unroll
            for (int mt = 0; mt < 2; ++mt) {
                ldsm4(ah[mt], S + SM_QH + qoff[mt] + qeB);
                ldsm4(al[mt], S + SM_QL + qoff[mt] + qeB);
            }
            ldsm4(bh, KB + koff + keB);
            ldsm4(bl, KB + KLO_OFF + koff + keB);
#pragma unroll
            for (int mt = 0; mt < 2; ++mt) {
                mma16816(acc[mt][0], ah[mt], &bh[0]);
                mma16816(acc[mt][0], ah[mt], &bl[0]);
                mma16816(acc[mt][0], al[mt], &bh[0]);
                mma16816(acc[mt][1], ah[mt], &bh[2]);
                mma16816(acc[mt][1], ah[mt], &bl[2]);
                mma16816(acc[mt][1], al[mt], &bh[2]);
            }
        }
    }

    __syncthreads();
    float bias2[2][2];
#pragma unroll
    for (int nt = 0; nt < 2; ++nt)
#pragma unroll
        for (int j = 0; j < 2; ++j)
            bias2[nt][j] = __ldg(bias + f0 + kg * 16 + nt * 8 + (lane & 3) * 2 + j);
    __nv_bfloat16* sh = (__nv_bfloat16*)(smraw + SM_K);
    __nv_bfloat16* sl = (__nv_bfloat16*)(smraw + SM_K + 8192);
#pragma unroll
    for (int mt = 0; mt < 2; ++mt)
#pragma unroll
        for (int nt = 0; nt < 2; ++nt)
#pragma unroll
            for (int c = 0; c < 4; ++c) {
                const int row = mt * 16 + (lane >> 2) + (c >> 1) * 8;
                const int col = kg * 16 + nt * 8 + (lane & 3) * 2 + (c & 1);
                const float q = acc[mt][nt][c] + bias2[nt][c & 1];
                const __nv_bfloat16 h = __float2bfloat16_rn(q);
                sh[row * 128 + col] = h;
                sl[row * 128 + col] = __float2bfloat16_rn(q - __bfloat162float(h));
            }
    __syncthreads();
    {
        const int row = tid >> 3, seg = tid & 7;
        const size_t gbase = ((size_t)(b * NN + n0 + row)) * EE + f0 + seg * 16;
        const int sbase = row * 128 + seg * 16;
        *(uint4*)(Oh + gbase)     = *(uint4*)(sh + sbase);
        *(uint4*)(Oh + gbase + 8) = *(uint4*)(sh + sbase + 8);
        *(uint4*)(Ol + gbase)     = *(uint4*)(sl + sbase);
        *(uint4*)(Ol + gbase + 8) = *(uint4*)(sl + sbase + 8);
    }
}

// ---------------------------------------------------------------------------
__global__ __launch_bounds__(256) void kk_kernel()
{
    const int row = blockIdx.x * 8 + (threadIdx.x >> 5);
    const int lane = threadIdx.x & 31;
    const uint4* h4 = (const uint4*)(g_Khi + (size_t)row * EE);
    const uint4* l4 = (const uint4*)(g_Klo + (size_t)row * EE);
    float s = 0.f;
#pragma unroll
    for (int it = 0; it < 2; ++it) {
        uint4 h = h4[lane + it * 32], l = l4[lane + it * 32];
        const __nv_bfloat162* hp = (const __nv_bfloat162*)&h;
        const __nv_bfloat162* lp = (const __nv_bfloat162*)&l;
#pragma unroll
        for (int k = 0; k < 4; ++k) {
            float2 fh = __bfloat1622float2(hp[k]);
            float2 fl = __bfloat1622float2(lp[k]);
            float x = fh.x + fl.x, y = fh.y + fl.y;
            s = fmaf(x, x, fmaf(y, y, s));
        }
    }
#pragma unroll
    for (int off = 16; off; off >>= 1) s += __shfl_xor_sync(0xffffffffu, s, off);
    if (lane == 0) g_kk[row] = s;
}

// ---------------------------------------------------------------------------
// Phase 1: hi*hi approximate logits -> g_est (fp16). Unchanged from round 11.
// ---------------------------------------------------------------------------
#define P1_SMK 33280
#define P1_STAGE 10240
#define P1_TOTAL 53760

__global__ __launch_bounds__(256, 3) void est_kernel()
{
    extern __shared__ char smraw[];
    const u32 S = smem_u32(smraw);
    const int tid = threadIdx.x, kg = tid >> 5, lane = tid & 31;
    const int b = blockIdx.x >> 7, n0 = (blockIdx.x & 127) * 32;
    const int mbase = blockIdx.y * 512;

    {
        const char* qh = (const char*)(g_Qhi + (size_t)(b * NN + n0) * EE);
#pragma unroll
        for (int it = 0; it < 8; ++it) {
            const int i = tid + it * 256;
            const int row = i >> 6, g = (i & 63) * 16;
            cp16(S + row * QPITCH + g, qh + row * 1024 + g);
        }
        CP_COMMIT(); CP_WAIT0();
        __syncthreads();
    }

    const int laneQrow = (lane & 7) + ((lane >> 3) & 1) * 8;
    const int laneQcolB = (lane >> 4) * 16;
    const int laneKn = (lane & 7) + ((lane >> 4) & 1) * 8;
    const int laneKeB = ((lane >> 3) & 1) * 16;
    u32 qoff[2];
    qoff[0] = (u32)(laneQrow * QPITCH + laneQcolB);
    qoff[1] = qoff[0] + 16 * QPITCH;
    const u32 koff = (u32)((kg * 16 + laneKn) * KPITCH + laneKeB);
    const u32 fko = (u32)((kg * 16 + (lane >> 1)) * KPITCH + (lane & 1) * 32);
    const char* src_h = (const char*)g_Khi
        + ((size_t)(b * MM + mbase + kg * 16 + (lane >> 1))) * 1024 + (lane & 1) * 32;

    const float* kkb = g_kk + b * MM + mbase;
    __half* estb = g_est + ((size_t)(b * NN + n0)) * MM + mbase;

    float acc[2][2][4];
#pragma unroll
    for (int mt = 0; mt < 2; ++mt)
#pragma unroll
        for (int nt = 0; nt < 2; ++nt)
#pragma unroll
            for (int j = 0; j < 4; ++j) acc[mt][nt][j] = 0.f;

    cp16(S + P1_SMK + fko,      src_h);
    cp16(S + P1_SMK + fko + 16, src_h + 16);
    CP_COMMIT();

    for (int cc = 0; cc < 64; ++cc) {
        if (cc < 63) {
            const int nc = cc + 1;
            const u32 dst = S + P1_SMK + (u32)(nc & 1) * P1_STAGE + fko;
            const size_t go = (size_t)(nc >> 4) * 131072 + (size_t)(nc & 15) * 64;
            cp16(dst,      src_h + go);
            cp16(dst + 16, src_h + go + 16);
            CP_COMMIT();
            CP_WAIT1();
        } else {
            CP_WAIT0();
        }
        __syncwarp();

        const u32 KB = S + P1_SMK + (u32)(cc & 1) * P1_STAGE;
        const u32 chB = (u32)((cc & 15) * 64);
#pragma unroll
        for (int s = 0; s < 2; ++s) {
            const u32 qeB = chB + (u32)(s * 32);
            u32 ah[2][4], bh[4];
            ldsm4(ah[0], S + qoff[0] + qeB);
            ldsm4(ah[1], S + qoff[1] + qeB);
            ldsm4(bh, KB + koff + (u32)(s * 32));
#pragma unroll
            for (int mt = 0; mt < 2; ++mt) {
                mma16816(acc[mt][0], ah[mt], &bh[0]);
                mma16816(acc[mt][1], ah[mt], &bh[2]);
            }
        }

        if ((cc & 15) == 15) {
            const int m0 = (cc >> 4) * 128;
            const int c0 = kg * 16 + (lane & 3) * 2;
            const float kk0 = __ldg(kkb + m0 + c0);
            const float kk1 = __ldg(kkb + m0 + c0 + 1);
            const float kk2 = __ldg(kkb + m0 + c0 + 8);
            const float kk3 = __ldg(kkb + m0 + c0 + 9);
#pragma unroll
            for (int mt = 0; mt < 2; ++mt)
#pragma unroll
                for (int h = 0; h < 2; ++h) {
                    const int row = mt * 16 + h * 8 + (lane >> 2);
                    __half* ep = estb + (size_t)row * MM + m0 + c0;
                    float2 fa = make_float2(fmaf(2.f, acc[mt][0][h*2+0], -kk0),
                                            fmaf(2.f, acc[mt][0][h*2+1], -kk1));
                    float2 fb = make_float2(fmaf(2.f, acc[mt][1][h*2+0], -kk2),
                                            fmaf(2.f, acc[mt][1][h*2+1], -kk3));
                    *reinterpret_cast<__half2*>(ep)     = __float22half2_rn(fa);
                    *reinterpret_cast<__half2*>(ep + 8) = __float22half2_rn(fb);
                    acc[mt][0][h*2+0] = 0.f; acc[mt][0][h*2+1] = 0.f;
                    acc[mt][1][h*2+0] = 0.f; acc[mt][1][h*2+1] = 0.f;
                }
        }
    }
}

// ---------------------------------------------------------------------------
// Phase 2 (v2): single global pass into a 64-reg cache, in-register threshold
// scan, warp-cooperative exact recompute. One warp per q-row.
// ---------------------------------------------------------------------------
__global__ __launch_bounds__(256) void gather_kernel(const float* __restrict__ tgt,
                                                     float* __restrict__ out_corr)
{
    const int w = blockIdx.x * 8 + (threadIdx.x >> 5);   // b*NN + n
    const int lane = threadIdx.x & 31;
    const int b = w >> 12, n = w & (NN - 1);

    // q row slice (16 e per lane), exact reconstruct
    float qf[16];
    {
        const uint4* qh = (const uint4*)(g_Qhi + (size_t)w * EE + lane * 16);
        const uint4* ql = (const uint4*)(g_Qlo + (size_t)w * EE + lane * 16);
        uint4 H[2] = {qh[0], qh[1]}, L[2] = {ql[0], ql[1]};
#pragma unroll
        for (int g = 0; g < 2; ++g) {
            const __nv_bfloat162* hp = (const __nv_bfloat162*)&H[g];
            const __nv_bfloat162* lp = (const __nv_bfloat162*)&L[g];
#pragma unroll
            for (int j = 0; j < 4; ++j) {
                float2 fh = __bfloat1622float2(hp[j]);
                float2 fl = __bfloat1622float2(lp[j]);
                qf[g*8 + j*2 + 0] = fh.x + fl.x;
                qf[g*8 + j*2 + 1] = fh.y + fl.y;
            }
        }
    }

    // Pass 1: load est row into registers (lane covers keys it*256 + lane*8 .. +8)
    const __half* er = g_est + (size_t)w * MM;
    u32 cache[64];
    float rmax = -1e30f;
#pragma unroll
    for (int it = 0; it < 16; ++it) {
        uint4 v = *(const uint4*)(er + it * 256 + lane * 8);
        cache[it*4+0] = v.x; cache[it*4+1] = v.y;
        cache[it*4+2] = v.z; cache[it*4+3] = v.w;
        const __half2* hp = (const __half2*)&v;
#pragma unroll
        for (int j = 0; j < 4; ++j) {
            float2 f = __half22float2(hp[j]);
            rmax = fmaxf(rmax, fmaxf(f.x, f.y));
        }
    }
#pragma unroll
    for (int off = 16; off; off >>= 1)
        rmax = fmaxf(rmax, __shfl_xor_sync(0xffffffffu, rmax, off));
    const float T = rmax - 25.f;

    const float* kkb = g_kk + b * MM;
    const float* tb  = tgt + (size_t)b * 3 * MM;
    float m = -1e30f, sl = 0.f, o0 = 0.f, o1 = 0.f, o2 = 0.f;

    // Pass 2: in-register threshold scan, warp-enumerated exact recompute
#pragma unroll
    for (int it = 0; it < 16; ++it) {
        u32 mk = 0;
#pragma unroll
        for (int j = 0; j < 4; ++j) {
            float2 f = __half22float2(*(const __half2*)&cache[it*4+j]);
            if (f.x >= T) mk |= 1u << (j*2);
            if (f.y >= T) mk |= 1u << (j*2+1);
        }
        u32 wm = __ballot_sync(0xffffffffu, mk != 0);
        while (wm) {
            const int slane = __ffs(wm) - 1;
            wm &= wm - 1;
            u32 m8 = __shfl_sync(0xffffffffu, mk, slane);
            while (m8) {
                const int bit = __ffs(m8) - 1;
                m8 &= m8 - 1;
                const int kix = it * 256 + slane * 8 + bit;
                const uint4* kh = (const uint4*)(g_Khi + (size_t)(b * MM + kix) * EE + lane * 16);
                const uint4* kl = (const uint4*)(g_Klo + (size_t)(b * MM + kix) * EE + lane * 16);
                uint4 H[2] = {kh[0], kh[1]}, L[2] = {kl[0], kl[1]};
                float d = 0.f;
#pragma unroll
                for (int g = 0; g < 2; ++g) {
                    const __nv_bfloat162* hp = (const __nv_bfloat162*)&H[g];
                    const __nv_bfloat162* lp = (const __nv_bfloat162*)&L[g];
#pragma unroll
                    for (int j = 0; j < 4; ++j) {
                        float2 fh = __bfloat1622float2(hp[j]);
                        float2 fl = __bfloat1622float2(lp[j]);
                        d = fmaf(qf[g*8 + j*2 + 0], fh.x + fl.x, d);
                        d = fmaf(qf[g*8 + j*2 + 1], fh.y + fl.y, d);
                    }
                }
#pragma unroll
                for (int off = 16; off; off >>= 1)
                    d += __shfl_xor_sync(0xffffffffu, d, off);
                if (lane == 0) {
                    const float lg = fmaf(2.f, d, -__ldg(kkb + kix));
                    const float nm = fmaxf(m, lg);
                    const float sc = __expf(m - nm);
                    const float p  = __expf(lg - nm);
                    sl = sl * sc + p;
                    o0 = o0 * sc + p * __ldg(tb + kix);
                    o1 = o1 * sc + p * __ldg(tb + MM + kix);
                    o2 = o2 * sc + p * __ldg(tb + 2 * MM + kix);
                    m = nm;
                }
            }
        }
    }

    if (lane == 0) {
        const float inv = 1.f / sl;
        out_corr[(size_t)b * 3 * NN + n]          = o0 * inv;
        out_corr[(size_t)b * 3 * NN + NN + n]     = o1 * inv;
        out_corr[(size_t)b * 3 * NN + 2 * NN + n] = o2 * inv;
    }
}

__global__ void copy_src_kernel(const float* __restrict__ src, float* __restrict__ out)
{
    const int i = blockIdx.x * 256 + threadIdx.x;
    if (i < BB * 3 * NN) out[i] = src[i];
}

// ---------------------------------------------------------------------------
extern "C" void kernel_launch(void* const* d_in, const int* in_sizes, int n_in,
                              void* d_out, int out_size)
{
    const float* src_emb = (const float*)d_in[0];
    const float* tgt_emb = (const float*)d_in[1];
    const float* src     = (const float*)d_in[2];
    const float* tgt     = (const float*)d_in[3];
    const float* Wq      = (const float*)d_in[4];
    const float* bq      = (const float*)d_in[5];
    const float* Wk      = (const float*)d_in[6];
    const float* bk      = (const float*)d_in[7];
    float* out = (float*)d_out;

    const int corr_elems = BB * 3 * NN;
    const bool tuple_out = (out_size >= 2 * corr_elems);
    float* corr_out = tuple_out ? (out + corr_elems) : out;

    splitW_kernel<<<EE * EE / 1024, 256>>>(Wq, 0);
    splitW_kernel<<<EE * EE / 1024, 256>>>(Wk, 1);
    splitX_kernel<<<dim3(NN / 64, EE / 64, BB), 256>>>(src_emb, 0);
    splitX_kernel<<<dim3(MM / 64, EE / 64, BB), 256>>>(tgt_emb, 1);

    cudaFuncSetAttribute(projmma_kernel, cudaFuncAttributeMaxDynamicSharedMemorySize,
                         SMEM_TOTAL);
    projmma_kernel<<<dim3(256, 4), 256, SMEM_TOTAL>>>(bq, 0);
    projmma_kernel<<<dim3(256, 4), 256, SMEM_TOTAL>>>(bk, 1);

    kk_kernel<<<BB * MM / 8, 256>>>();

    cudaFuncSetAttribute(est_kernel, cudaFuncAttributeMaxDynamicSharedMemorySize,
                         P1_TOTAL);
    est_kernel<<<dim3(256, 8), 256, P1_TOTAL>>>();

    gather_kernel<<<BB * NN / 8, 256>>>(tgt, corr_out);

    if (tuple_out)
        copy_src_kernel<<<(corr_elems + 255) / 256, 256>>>(src, out);
}